// round 8
// baseline (speedup 1.0000x reference)
#include <cuda_runtime.h>
#include <cuda_fp16.h>
#include <math.h>
#include <stdint.h>

typedef unsigned long long u64;

#define Bsz   1024
#define Pn    20
#define Ln    3
#define Tn    5
#define En    128
#define Nseq  (Bsz*Pn)          /* 20480 */
#define NPL   (Bsz*Pn*Ln)       /* 61440 */
#define NREL  60
#define DDOC  768
#define DENT  100
#define KPAD  112
#define MTOT  (NPL + 2*Bsz)     /* 63488 = 496*128 */

// ---------------- device scratch ----------------
__device__ __half g_AE [(size_t)MTOT * 128];
__device__ __half g_Bn [512 * 128];
__device__ __half g_Bh [512 * 128];
__device__ __half g_Wec[128 * KPAD];
__device__ float  g_relGb[NREL * 512];          // permuted quads
__device__ __half g_G16 [(size_t)MTOT * 512];   // permuted quads

// ---- fast transcendentals ----
__device__ __forceinline__ float tanha(float x) {
    float y; asm("tanh.approx.f32 %0, %1;" : "=f"(y) : "f"(x)); return y;
}
__device__ __forceinline__ float siga(float x) {
    return fmaf(tanha(x * 0.5f), 0.5f, 0.5f);
}

// ---- f32x2 helpers ----
__device__ __forceinline__ u64 ffma2(u64 a, u64 b, u64 c) {
    u64 d; asm("fma.rn.f32x2 %0, %1, %2, %3;" : "=l"(d) : "l"(a), "l"(b), "l"(c)); return d;
}
__device__ __forceinline__ u64 dup2(float x) {
    u64 d; unsigned xi = __float_as_uint(x);
    asm("mov.b64 %0, {%1, %1};" : "=l"(d) : "r"(xi)); return d;
}
__device__ __forceinline__ u64 pack2(float lo, float hi) {
    u64 d; asm("mov.b64 %0, {%1, %2};" : "=l"(d) : "r"(__float_as_uint(lo)), "r"(__float_as_uint(hi)));
    return d;
}
__device__ __forceinline__ float2 up2(u64 v) {
    unsigned lo, hi; asm("mov.b64 {%0, %1}, %2;" : "=r"(lo), "=r"(hi) : "l"(v));
    return make_float2(__uint_as_float(lo), __uint_as_float(hi));
}

// ---- mma / ldmatrix ----
__device__ __forceinline__ uint32_t s2u(const void* p) {
    uint32_t a;
    asm("{ .reg .u64 t; cvta.to.shared.u64 t, %1; cvt.u32.u64 %0, t; }" : "=r"(a) : "l"(p));
    return a;
}
__device__ __forceinline__ void ldmA(uint32_t* r, uint32_t addr) {
    asm volatile("ldmatrix.sync.aligned.m8n8.x4.shared.b16 {%0,%1,%2,%3}, [%4];"
                 : "=r"(r[0]), "=r"(r[1]), "=r"(r[2]), "=r"(r[3]) : "r"(addr));
}
__device__ __forceinline__ void ldmB(uint32_t* r, uint32_t addr) {
    asm volatile("ldmatrix.sync.aligned.m8n8.x2.shared.b16 {%0,%1}, [%2];"
                 : "=r"(r[0]), "=r"(r[1]) : "r"(addr));
}
__device__ __forceinline__ void mma16816(float* d, const uint32_t* a, const uint32_t* b) {
    asm volatile("mma.sync.aligned.m16n8k16.row.col.f32.f16.f16.f32 "
        "{%0,%1,%2,%3}, {%4,%5,%6,%7}, {%8,%9}, {%0,%1,%2,%3};"
        : "+f"(d[0]), "+f"(d[1]), "+f"(d[2]), "+f"(d[3])
        : "r"(a[0]), "r"(a[1]), "r"(a[2]), "r"(a[3]), "r"(b[0]), "r"(b[1]));
}

#define ASTR  272
#define CKSTR 240
#define DSTR  10

// ---------------- K0: setup = weight pack (blocks 0..127) + relation path (128..187) ----------
__global__ void k_setup(const float* __restrict__ W_ih, const float* __restrict__ W_hh,
                        const float* __restrict__ ec_W,
                        const float* __restrict__ rel_table,
                        const float* __restrict__ rc_W, const float* __restrict__ rc_b,
                        const float* __restrict__ b_ih, const float* __restrict__ b_hh) {
    int tid = threadIdx.x;
    if (blockIdx.x < 128) {
        int idx = blockIdx.x * 512 + tid;
        if (idx < 128 * KPAD) {
            int c = idx / KPAD, k = idx - c * KPAD;
            g_Wec[idx] = (k < DENT) ? __float2half_rn(ec_W[k * 128 + c]) : __half(0.0f);
        }
        int c = idx >> 7, k = idx & 127;
        int row = (c & 3) * 128 + (c >> 2);
        g_Bn[c * 128 + k] = __float2half_rn(W_ih[row * 256 + k]);
        g_Bh[c * 128 + k] = __float2half_rn(W_hh[row * 128 + k]);
    } else {
        __shared__ float rr[DENT];
        __shared__ float rc[En];
        int rrow = blockIdx.x - 128;     // 0..59
        if (tid < DENT) rr[tid] = rel_table[rrow * DENT + tid];
        __syncthreads();
        if (tid < En) {
            float s = rc_b[tid];
            for (int k = 0; k < DENT; k++) s += rr[k] * rc_W[k * En + tid];
            rc[tid] = tanhf(s);
        }
        __syncthreads();
        int c = tid;
        int j = c >> 2, g = c & 3;
        int gidx = g * 128 + j;
        float s = b_ih[gidx] + b_hh[gidx];
        const float* wrow = W_ih + (size_t)gidx * 256 + 128;
        for (int k = 0; k < En; k++) s += rc[k] * wrow[k];
        int q = c >> 2;
        int p = (q & ~31) | ((q & 1) << 4) | ((q & 31) >> 1);
        g_relGb[rrow * 512 + p * 4 + g] = s;
    }
}

// ---------------- K1: news compress -> f16 rows ----------------
__global__ void k_news(const int* __restrict__ item1, const int* __restrict__ item2,
                       const float* __restrict__ doc_table,
                       const float* __restrict__ W1, const float* __restrict__ b1,
                       const float* __restrict__ W2, const float* __restrict__ b2) {
    __shared__ __align__(16) float dsp[DDOC * DSTR];
    __shared__ __align__(16) float h1p[En * DSTR];
    __shared__ int items[8];
    int r0 = blockIdx.x * 8;
    int tid = threadIdx.x;
    if (tid < 8) {
        int row = r0 + tid;
        items[tid] = (row < Bsz) ? item1[row] : item2[row - Bsz];
    }
    __syncthreads();
    for (int k = tid; k < DDOC; k += 128) {
#pragma unroll
        for (int r = 0; r < 8; r++)
            dsp[k * DSTR + r] = doc_table[(size_t)items[r] * DDOC + k];
    }
    __syncthreads();
    u64 acc2[4];
    u64 bd = dup2(b1[tid]);
#pragma unroll
    for (int p = 0; p < 4; p++) acc2[p] = bd;
    for (int k = 0; k < DDOC; k++) {
        u64 wd = dup2(W1[k * En + tid]);
        const u64* hp = (const u64*)&dsp[k * DSTR];
#pragma unroll
        for (int p = 0; p < 4; p++) acc2[p] = ffma2(hp[p], wd, acc2[p]);
    }
#pragma unroll
    for (int p = 0; p < 4; p++) {
        float2 a = up2(acc2[p]);
        h1p[tid * DSTR + 2 * p]     = (a.x > 0.0f) ? a.x : expm1f(a.x);
        h1p[tid * DSTR + 2 * p + 1] = (a.y > 0.0f) ? a.y : expm1f(a.y);
    }
    __syncthreads();
    u64 bd2 = dup2(b2[tid]);
#pragma unroll
    for (int p = 0; p < 4; p++) acc2[p] = bd2;
    for (int k = 0; k < En; k++) {
        u64 wd = dup2(W2[k * En + tid]);
        const u64* hp = (const u64*)&h1p[k * DSTR];
#pragma unroll
        for (int p = 0; p < 4; p++) acc2[p] = ffma2(hp[p], wd, acc2[p]);
    }
#pragma unroll
    for (int p = 0; p < 4; p++) {
        float2 a = up2(acc2[p]);
        g_AE[(size_t)(NPL + r0 + 2 * p)     * En + tid] = __float2half_rn(tanhf(a.x));
        g_AE[(size_t)(NPL + r0 + 2 * p + 1) * En + tid] = __float2half_rn(tanhf(a.y));
    }
}

// ---------------- K3: entity gather + HMMA compress (2 CTA/SM) ----------------
#define SMC_A 0
#define SMC_B (128 * CKSTR)
#define SMC_TOTAL (2 * 128 * CKSTR)
__global__ __launch_bounds__(512, 2) void k_compress_mma(const int* __restrict__ paths,
                                                         const float* __restrict__ ent_table,
                                                         const float* __restrict__ ec_b) {
    extern __shared__ char sm[];
    __shared__ int spath[128];
    int tid = threadIdx.x, w = tid >> 5, l = tid & 31;
    int wm = w & 3, wn = w >> 2;
    int row0 = blockIdx.x * 128;

    if (tid < 128) spath[tid] = paths[row0 + tid];
    __syncthreads();
    for (int idx = tid; idx < 128 * 25; idx += 512) {
        int r = idx / 25, k4 = idx - r * 25;
        float4 v = *(const float4*)(ent_table + (size_t)spath[r] * DENT + k4 * 4);
        uint2 u;
        *((__half2*)&u.x) = __floats2half2_rn(v.x, v.y);
        *((__half2*)&u.y) = __floats2half2_rn(v.z, v.w);
        *(uint2*)(sm + SMC_A + r * CKSTR + k4 * 8) = u;
    }
    for (int idx = tid; idx < 128 * 3; idx += 512) {
        int r = idx / 3, j = idx - r * 3;
        *(uint2*)(sm + SMC_A + r * CKSTR + 200 + j * 8) = make_uint2(0u, 0u);
    }
    for (int idx = tid; idx < 128 * 28; idx += 512) {
        int r = idx / 28, j = idx - r * 28;
        *(uint2*)(sm + SMC_B + r * CKSTR + j * 8) = ((const uint2*)g_Wec)[idx];
    }
    __syncthreads();

    uint32_t base = s2u(sm);
    int g8 = l & 7;
    uint32_t aBase = base + SMC_A + (uint32_t)(wm * 32 + g8 + ((l >> 3) & 1) * 8) * CKSTR
                   + ((l >> 4) & 1) * 16;
    uint32_t bBase = base + SMC_B + (uint32_t)(wn * 32 + g8) * CKSTR + ((l >> 3) & 1) * 16;

    float acc[2][4][4];
#pragma unroll
    for (int mt = 0; mt < 2; mt++)
#pragma unroll
        for (int nt = 0; nt < 4; nt++)
#pragma unroll
            for (int q = 0; q < 4; q++) acc[mt][nt][q] = 0.0f;

#pragma unroll
    for (int kt = 0; kt < 7; kt++) {
        uint32_t a[2][4];
        ldmA(a[0], aBase + kt * 32);
        ldmA(a[1], aBase + 16 * CKSTR + kt * 32);
#pragma unroll
        for (int nt = 0; nt < 4; nt++) {
            uint32_t b[2];
            ldmB(b, bBase + nt * 8 * CKSTR + kt * 32);
            mma16816(acc[0][nt], a[0], b);
            mma16816(acc[1][nt], a[1], b);
        }
    }
    __syncthreads();

    int tg = l & 3, gg = l >> 2;
#pragma unroll
    for (int mt = 0; mt < 2; mt++) {
        int r = wm * 32 + mt * 16 + gg;
#pragma unroll
        for (int nt = 0; nt < 4; nt++) {
            int cc = wn * 32 + nt * 8 + 2 * tg;
            float b0 = __ldg(ec_b + cc), b1 = __ldg(ec_b + cc + 1);
            *(__half2*)(sm + r * ASTR + cc * 2) =
                __floats2half2_rn(tanha(acc[mt][nt][0] + b0), tanha(acc[mt][nt][1] + b1));
            *(__half2*)(sm + (r + 8) * ASTR + cc * 2) =
                __floats2half2_rn(tanha(acc[mt][nt][2] + b0), tanha(acc[mt][nt][3] + b1));
        }
    }
    __syncthreads();
    for (int it = tid; it < 128 * 16; it += 512) {
        int r = it >> 4, bb = it & 15;
        uint4 v = *(uint4*)(sm + r * ASTR + bb * 16);
        *(uint4*)((char*)g_AE + (size_t)(row0 + r) * 256 + bb * 16) = v;
    }
}

// ---------------- K4: HMMA GEMM, 128x128 tiles, 2 CTA/SM ----------------
#define SMG_A 0
#define SMG_B (128 * ASTR)
#define SMG_TOTAL (2 * 128 * ASTR)        /* 69632 */
__global__ __launch_bounds__(512, 2) void k_gemm_mma() {
    extern __shared__ char sm[];
    int tid = threadIdx.x, w = tid >> 5, l = tid & 31;
    int wm = w & 3, wn = w >> 2;
    int row0 = blockIdx.x * 128;
    int n0b  = blockIdx.y * 128;

    const uint4* Ag = (const uint4*)g_AE;
    for (int idx = tid; idx < 128 * 16; idx += 512) {
        int r = idx >> 4, c4 = idx & 15;
        *(uint4*)(sm + SMG_A + r * ASTR + c4 * 16) = Ag[(size_t)(row0 + r) * 16 + c4];
    }
    const uint4* Bg = (const uint4*)g_Bn;
    for (int idx = tid; idx < 128 * 16; idx += 512) {
        int n = idx >> 4, c4 = idx & 15;
        *(uint4*)(sm + SMG_B + n * ASTR + c4 * 16) = Bg[(size_t)(n0b + n) * 16 + c4];
    }
    __syncthreads();

    uint32_t base = s2u(sm);
    int g8 = l & 7;
    uint32_t aBase = base + SMG_A + (uint32_t)(wm * 32 + g8 + ((l >> 3) & 1) * 8) * ASTR
                   + ((l >> 4) & 1) * 16;
    uint32_t bBase = base + SMG_B + (uint32_t)(wn * 32 + g8) * ASTR + ((l >> 3) & 1) * 16;

    float acc[2][4][4];
#pragma unroll
    for (int mt = 0; mt < 2; mt++)
#pragma unroll
        for (int nt = 0; nt < 4; nt++)
#pragma unroll
            for (int q = 0; q < 4; q++) acc[mt][nt][q] = 0.0f;

#pragma unroll
    for (int kt = 0; kt < 8; kt++) {
        uint32_t a[2][4];
        ldmA(a[0], aBase + kt * 32);
        ldmA(a[1], aBase + 16 * ASTR + kt * 32);
#pragma unroll
        for (int nt = 0; nt < 4; nt++) {
            uint32_t b[2];
            ldmB(b, bBase + nt * 8 * ASTR + kt * 32);
            mma16816(acc[0][nt], a[0], b);
            mma16816(acc[1][nt], a[1], b);
        }
    }
    __syncthreads();   // A/B dead; overlay C staging (128 rows x 256B, stride ASTR)

    int tg = l & 3, gg = l >> 2;
#pragma unroll
    for (int mt = 0; mt < 2; mt++) {
        int r = wm * 32 + mt * 16 + gg;
#pragma unroll
        for (int nt = 0; nt < 4; nt++) {
            int qg = wn * 8 + nt * 2 + (tg >> 1);                 // local quad 0..31
            int pl = ((qg & 1) << 4) | (qg >> 1);
            *(__half2*)(sm + r * ASTR + pl * 8 + (tg & 1) * 4) =
                __floats2half2_rn(acc[mt][nt][0], acc[mt][nt][1]);
            *(__half2*)(sm + (r + 8) * ASTR + pl * 8 + (tg & 1) * 4) =
                __floats2half2_rn(acc[mt][nt][2], acc[mt][nt][3]);
        }
    }
    __syncthreads();
    for (int it = tid; it < 128 * 16; it += 512) {
        int r = it >> 4, bb = it & 15;
        uint4 v = *(uint4*)(sm + r * ASTR + bb * 16);
        *(uint4*)((char*)g_G16 + (size_t)(row0 + r) * 1024 + (size_t)n0b * 2 + bb * 16) = v;
    }
}

// ---------------- K5: HMMA LSTM + fused MLP (quarter chunks, no spills) ----------------
#define SML_A0 0
#define SML_A1 (64 * ASTR)
#define SML_B  (2 * 64 * ASTR)
#define SML_W1 SML_B
#define SML_PART (SML_B + 512 * ASTR)
#define SML_TOTAL (SML_PART + 2048)
__global__ __launch_bounds__(512, 1) void k_lstm_mma(const int* __restrict__ edges,
                                                     const float* __restrict__ mlp_W1,
                                                     const float* __restrict__ mlp_b1,
                                                     const float* __restrict__ mlp_W2,
                                                     const float* __restrict__ mlp_b2,
                                                     float* __restrict__ scores_out) {
    extern __shared__ char sm[];
    int tid = threadIdx.x, w = tid >> 5, l = tid & 31;
    int wm = w & 3, wn = w >> 2;
    int n0 = blockIdx.x * 64;
    int g8 = l & 7, tg = l & 3, gg = l >> 2;
    int odd = tg & 1;
    int par = tg >> 1;

    const uint4* Bg = (const uint4*)g_Bh;
    for (int idx = tid; idx < 512 * 16; idx += 512) {
        int n = idx >> 4, c4 = idx & 15;
        *(uint4*)(sm + SML_B + n * ASTR + c4 * 16) = Bg[(size_t)n * 16 + c4];
    }
    __syncthreads();

    uint32_t base = s2u(sm);
    uint32_t aLane = (uint32_t)(wm * 16 + g8 + ((l >> 3) & 1) * 8) * ASTR + ((l >> 4) & 1) * 16;
    uint32_t bBase = base + SML_B + (uint32_t)(wn * 128 + g8) * ASTR + ((l >> 3) & 1) * 16;

    int r_loc = wm * 16 + gg + odd * 8;
    int seq = n0 + r_loc;
    int bIdx = seq / Pn;

    float cst[16];
#pragma unroll
    for (int q = 0; q < 16; q++) cst[q] = 0.0f;

    for (int t = 0; t < Tn; t++) {
        uint32_t aRd = base + ((t & 1) ? SML_A0 : SML_A1) + aLane;
        char* hWr = sm + ((t & 1) ? SML_A1 : SML_A0);
        int rowG = (t == 0) ? NPL + bIdx
                 : (t == 4) ? NPL + Bsz + bIdx
                 : seq * Ln + (t - 1);
        int e = (t < Ln) ? edges[seq * Ln + t] : 0;
        const uint4* gp = (const uint4*)((const char*)g_G16 + (size_t)rowG * 1024
                                         + (size_t)(wn * 32 + par * 16) * 8);
        const float4* rp = (const float4*)(g_relGb + (size_t)e * 512
                                           + (wn * 32 + par * 16) * 4);

#pragma unroll
        for (int qc = 0; qc < 4; qc++) {      // 32-col chunks
            uint4 gu[2];
            gu[0] = gp[qc * 2];
            gu[1] = gp[qc * 2 + 1];

            float acc[4][4];
#pragma unroll
            for (int ni = 0; ni < 4; ni++)
#pragma unroll
                for (int q = 0; q < 4; q++) acc[ni][q] = 0.0f;
            if (t > 0) {
#pragma unroll
                for (int kt = 0; kt < 8; kt++) {
                    uint32_t a[4];
                    ldmA(a, aRd + kt * 32);
#pragma unroll
                    for (int ni = 0; ni < 4; ni++) {
                        uint32_t b[2];
                        ldmB(b, bBase + (qc * 4 + ni) * 8 * ASTR + kt * 32);
                        mma16816(acc[ni], a, b);
                    }
                }
            }
#pragma unroll
            for (int ni = 0; ni < 4; ni++) {
                int nt = qc * 4 + ni;
                float d0 = acc[ni][0], d1 = acc[ni][1];
                float d2 = acc[ni][2], d3 = acc[ni][3];
                float x0 = __shfl_xor_sync(0xffffffffu, d0, 1);
                float x1 = __shfl_xor_sync(0xffffffffu, d1, 1);
                float x2 = __shfl_xor_sync(0xffffffffu, d2, 1);
                float x3 = __shfl_xor_sync(0xffffffffu, d3, 1);
                float gi = odd ? x2 : d0;
                float gf = odd ? x3 : d1;
                float gG = odd ? d2 : x0;
                float gO = odd ? d3 : x1;
                __half2 hif = ((const __half2*)&gu[ni >> 1])[(ni & 1) * 2 + 0];
                __half2 hgo = ((const __half2*)&gu[ni >> 1])[(ni & 1) * 2 + 1];
                float2 fif = __half22float2(hif);
                float2 fgo = __half22float2(hgo);
                float4 r4 = rp[nt];
                gi += fif.x + r4.x;
                gf += fif.y + r4.y;
                gG += fgo.x + r4.z;
                gO += fgo.y + r4.w;
                cst[nt] = siga(gf) * cst[nt] + siga(gi) * tanha(gG);
                float hv = siga(gO) * tanha(cst[nt]);
                int q = wn * 32 + nt * 2 + par;
                *(__half*)(hWr + r_loc * ASTR + q * 2) = __float2half_rn(hv);
            }
        }
        __syncthreads();
    }

    // ---- fused MLP: final h in buffer A0 ----
    float* sW1 = (float*)(sm + SML_W1);
    for (int idx = tid; idx < 128 * 128; idx += 512) sW1[idx] = mlp_W1[idx];
    __syncthreads();

    int m = tid & 63, jb = (tid >> 6) * 16;
    u64 m1[8];
#pragma unroll
    for (int p = 0; p < 8; p++) m1[p] = pack2(mlp_b1[jb + 2 * p], mlp_b1[jb + 2 * p + 1]);
    const __half* hrow = (const __half*)(sm + SML_A0 + m * ASTR);
#pragma unroll 4
    for (int k = 0; k < 128; k++) {
        u64 hd = dup2(__half2float(hrow[k]));
        const u64* wp = (const u64*)&sW1[k * 128 + jb];
#pragma unroll
        for (int p = 0; p < 8; p++) m1[p] = ffma2(wp[p], hd, m1[p]);
    }
    float v = 0.0f;
#pragma unroll
    for (int p = 0; p < 8; p++) {
        float2 a = up2(m1[p]);
        v += fmaxf(a.x, 0.0f) * mlp_W2[jb + 2 * p]
           + fmaxf(a.y, 0.0f) * mlp_W2[jb + 2 * p + 1];
    }
    float* part = (float*)(sm + SML_PART);
    part[m * 8 + (tid >> 6)] = v;
    __syncthreads();
    if (tid < 64) {
        float s = mlp_b2[0];
#pragma unroll
        for (int p = 0; p < 8; p++) s += part[tid * 8 + p];
        scores_out[n0 + tid] = s;
    }
}

// ---------------- K7: logsumexp + BCE ----------------
__global__ void k_final(const float* __restrict__ label, float* __restrict__ out) {
    __shared__ float red[Bsz];
    int b = threadIdx.x;
    const float* sc = out + 1 + Bsz + b * Pn;
    float mx = -1e30f;
#pragma unroll
    for (int p = 0; p < Pn; p++) mx = fmaxf(mx, sc[p] * 0.5f);
    float s = 0.0f;
#pragma unroll
    for (int p = 0; p < Pn; p++) s += expf(sc[p] * 0.5f - mx);
    float lse = mx + logf(s);
    float pr = 1.0f / (1.0f + expf(-lse));
    out[1 + b] = pr;
    float pc = fminf(fmaxf(pr, 1e-7f), 1.0f - 1e-7f);
    float lb = label[b];
    red[b] = -(lb * logf(pc) + (1.0f - lb) * logf(1.0f - pc));
    __syncthreads();
    for (int st = Bsz / 2; st > 0; st >>= 1) {
        if (b < st) red[b] += red[b + st];
        __syncthreads();
    }
    if (b == 0) out[0] = red[0] / (float)Bsz;
}

// ---------------- launch ----------------
extern "C" void kernel_launch(void* const* d_in, const int* in_sizes, int n_in,
                              void* d_out, int out_size) {
    const int*   item1     = (const int*)d_in[0];
    const int*   item2     = (const int*)d_in[1];
    const int*   paths     = (const int*)d_in[2];
    const int*   edges     = (const int*)d_in[3];
    const float* label     = (const float*)d_in[4];
    const float* doc_table = (const float*)d_in[5];
    const float* ent_table = (const float*)d_in[6];
    const float* rel_table = (const float*)d_in[7];
    const float* nc_W1 = (const float*)d_in[8];
    const float* nc_b1 = (const float*)d_in[9];
    const float* nc_W2 = (const float*)d_in[10];
    const float* nc_b2 = (const float*)d_in[11];
    const float* ec_W  = (const float*)d_in[12];
    const float* ec_b  = (const float*)d_in[13];
    const float* rc_W  = (const float*)d_in[14];
    const float* rc_b  = (const float*)d_in[15];
    const float* W_ih  = (const float*)d_in[16];
    const float* W_hh  = (const float*)d_in[17];
    const float* b_ih  = (const float*)d_in[18];
    const float* b_hh  = (const float*)d_in[19];
    const float* mlp_W1 = (const float*)d_in[20];
    const float* mlp_b1 = (const float*)d_in[21];
    const float* mlp_W2 = (const float*)d_in[22];
    const float* mlp_b2 = (const float*)d_in[23];
    float* out = (float*)d_out;

    cudaFuncSetAttribute(k_compress_mma, cudaFuncAttributeMaxDynamicSharedMemorySize, SMC_TOTAL);
    cudaFuncSetAttribute(k_gemm_mma, cudaFuncAttributeMaxDynamicSharedMemorySize, SMG_TOTAL);
    cudaFuncSetAttribute(k_lstm_mma, cudaFuncAttributeMaxDynamicSharedMemorySize, SML_TOTAL);

    k_setup<<<188, 512>>>(W_ih, W_hh, ec_W, rel_table, rc_W, rc_b, b_ih, b_hh);
    k_news<<<2 * Bsz / 8, 128>>>(item1, item2, doc_table, nc_W1, nc_b1, nc_W2, nc_b2);
    k_compress_mma<<<NPL / 128, 512, SMC_TOTAL>>>(paths, ent_table, ec_b);
    k_gemm_mma<<<dim3(MTOT / 128, 4), 512, SMG_TOTAL>>>();
    k_lstm_mma<<<Nseq / 64, 512, SML_TOTAL>>>(edges, mlp_W1, mlp_b1, mlp_W2, mlp_b2,
                                              out + 1 + Bsz);
    k_final<<<1, Bsz>>>(label, out);
}

// round 9
// speedup vs baseline: 1.1742x; 1.1742x over previous
#include <cuda_runtime.h>
#include <cuda_fp16.h>
#include <math.h>
#include <stdint.h>

typedef unsigned long long u64;

#define Bsz   1024
#define Pn    20
#define Ln    3
#define Tn    5
#define En    128
#define Nseq  (Bsz*Pn)          /* 20480 */
#define NPL   (Bsz*Pn*Ln)       /* 61440 */
#define NREL  60
#define DDOC  768
#define DENT  100
#define KPAD  112
#define MTOT  (NPL + 2*Bsz)     /* 63488 = 496*128 */

// ---------------- device scratch ----------------
__device__ __half g_AE [(size_t)MTOT * 128];
__device__ __half g_Bn [512 * 128];
__device__ __half g_Bh [512 * 128];
__device__ __half g_Wec[128 * KPAD];
__device__ float  g_WTrel[128 * 512];           // f32 [k][c] (coalesced for k_rel)
__device__ float  g_relGb[NREL * 512];          // permuted quads
__device__ __half g_G16 [(size_t)MTOT * 512];   // permuted quads

// ---- fast transcendentals ----
__device__ __forceinline__ float tanha(float x) {
    float y; asm("tanh.approx.f32 %0, %1;" : "=f"(y) : "f"(x)); return y;
}
__device__ __forceinline__ float siga(float x) {
    return fmaf(tanha(x * 0.5f), 0.5f, 0.5f);
}

// ---- f32x2 helpers ----
__device__ __forceinline__ u64 ffma2(u64 a, u64 b, u64 c) {
    u64 d; asm("fma.rn.f32x2 %0, %1, %2, %3;" : "=l"(d) : "l"(a), "l"(b), "l"(c)); return d;
}
__device__ __forceinline__ u64 dup2(float x) {
    u64 d; unsigned xi = __float_as_uint(x);
    asm("mov.b64 %0, {%1, %1};" : "=l"(d) : "r"(xi)); return d;
}
__device__ __forceinline__ u64 pack2(float lo, float hi) {
    u64 d; asm("mov.b64 %0, {%1, %2};" : "=l"(d) : "r"(__float_as_uint(lo)), "r"(__float_as_uint(hi)));
    return d;
}
__device__ __forceinline__ float2 up2(u64 v) {
    unsigned lo, hi; asm("mov.b64 {%0, %1}, %2;" : "=r"(lo), "=r"(hi) : "l"(v));
    return make_float2(__uint_as_float(lo), __uint_as_float(hi));
}

// ---- mma / ldmatrix ----
__device__ __forceinline__ uint32_t s2u(const void* p) {
    uint32_t a;
    asm("{ .reg .u64 t; cvta.to.shared.u64 t, %1; cvt.u32.u64 %0, t; }" : "=r"(a) : "l"(p));
    return a;
}
__device__ __forceinline__ void ldmA(uint32_t* r, uint32_t addr) {
    asm volatile("ldmatrix.sync.aligned.m8n8.x4.shared.b16 {%0,%1,%2,%3}, [%4];"
                 : "=r"(r[0]), "=r"(r[1]), "=r"(r[2]), "=r"(r[3]) : "r"(addr));
}
__device__ __forceinline__ void ldmB(uint32_t* r, uint32_t addr) {
    asm volatile("ldmatrix.sync.aligned.m8n8.x2.shared.b16 {%0,%1}, [%2];"
                 : "=r"(r[0]), "=r"(r[1]) : "r"(addr));
}
__device__ __forceinline__ void mma16816(float* d, const uint32_t* a, const uint32_t* b) {
    asm volatile("mma.sync.aligned.m16n8k16.row.col.f32.f16.f16.f32 "
        "{%0,%1,%2,%3}, {%4,%5,%6,%7}, {%8,%9}, {%0,%1,%2,%3};"
        : "+f"(d[0]), "+f"(d[1]), "+f"(d[2]), "+f"(d[3])
        : "r"(a[0]), "r"(a[1]), "r"(a[2]), "r"(a[3]), "r"(b[0]), "r"(b[1]));
}

#define ASTR  272
#define CKSTR 240
#define DSTR  10

// ---------------- K0: transpose + pack weights (coalesced) ----------------
__global__ void k_transpose(const float* __restrict__ W_ih, const float* __restrict__ W_hh,
                            const float* __restrict__ ec_W) {
    int idx = blockIdx.x * blockDim.x + threadIdx.x;
    if (idx < 128 * KPAD) {
        int c = idx / KPAD, k = idx - c * KPAD;
        g_Wec[idx] = (k < DENT) ? __float2half_rn(ec_W[k * 128 + c]) : __half(0.0f);
    }
    if (idx >= 512 * 128) return;
    int c = idx >> 7, k = idx & 127;
    int row = (c & 3) * 128 + (c >> 2);
    g_Bn[c * 128 + k] = __float2half_rn(W_ih[row * 256 + k]);
    g_Bh[c * 128 + k] = __float2half_rn(W_hh[row * 128 + k]);
    g_WTrel[k * 512 + c] = W_ih[row * 256 + 128 + k];
}

// ---------------- K1: news compress -> f16 rows ----------------
__global__ void k_news(const int* __restrict__ item1, const int* __restrict__ item2,
                       const float* __restrict__ doc_table,
                       const float* __restrict__ W1, const float* __restrict__ b1,
                       const float* __restrict__ W2, const float* __restrict__ b2) {
    __shared__ __align__(16) float dsp[DDOC * DSTR];
    __shared__ __align__(16) float h1p[En * DSTR];
    __shared__ int items[8];
    int r0 = blockIdx.x * 8;
    int tid = threadIdx.x;
    if (tid < 8) {
        int row = r0 + tid;
        items[tid] = (row < Bsz) ? item1[row] : item2[row - Bsz];
    }
    __syncthreads();
    for (int k = tid; k < DDOC; k += 128) {
#pragma unroll
        for (int r = 0; r < 8; r++)
            dsp[k * DSTR + r] = doc_table[(size_t)items[r] * DDOC + k];
    }
    __syncthreads();
    u64 acc2[4];
    u64 bd = dup2(b1[tid]);
#pragma unroll
    for (int p = 0; p < 4; p++) acc2[p] = bd;
    for (int k = 0; k < DDOC; k++) {
        u64 wd = dup2(W1[k * En + tid]);
        const u64* hp = (const u64*)&dsp[k * DSTR];
#pragma unroll
        for (int p = 0; p < 4; p++) acc2[p] = ffma2(hp[p], wd, acc2[p]);
    }
#pragma unroll
    for (int p = 0; p < 4; p++) {
        float2 a = up2(acc2[p]);
        h1p[tid * DSTR + 2 * p]     = (a.x > 0.0f) ? a.x : expm1f(a.x);
        h1p[tid * DSTR + 2 * p + 1] = (a.y > 0.0f) ? a.y : expm1f(a.y);
    }
    __syncthreads();
    u64 bd2 = dup2(b2[tid]);
#pragma unroll
    for (int p = 0; p < 4; p++) acc2[p] = bd2;
    for (int k = 0; k < En; k++) {
        u64 wd = dup2(W2[k * En + tid]);
        const u64* hp = (const u64*)&h1p[k * DSTR];
#pragma unroll
        for (int p = 0; p < 4; p++) acc2[p] = ffma2(hp[p], wd, acc2[p]);
    }
#pragma unroll
    for (int p = 0; p < 4; p++) {
        float2 a = up2(acc2[p]);
        g_AE[(size_t)(NPL + r0 + 2 * p)     * En + tid] = __float2half_rn(tanhf(a.x));
        g_AE[(size_t)(NPL + r0 + 2 * p + 1) * En + tid] = __float2half_rn(tanhf(a.y));
    }
}

// ---------------- K2: relation compress + gate projection (coalesced WTrel) ----------------
__global__ void k_rel(const float* __restrict__ rel_table,
                      const float* __restrict__ W, const float* __restrict__ b,
                      const float* __restrict__ b_ih, const float* __restrict__ b_hh) {
    __shared__ float rr[DENT];
    __shared__ float rc[En];
    int row = blockIdx.x, tid = threadIdx.x;
    if (tid < DENT) rr[tid] = rel_table[row * DENT + tid];
    __syncthreads();
    if (tid < En) {
        float s = b[tid];
        for (int k = 0; k < DENT; k++) s += rr[k] * W[k * En + tid];
        rc[tid] = tanhf(s);
    }
    __syncthreads();
    int c = tid;
    int j = c >> 2, g = c & 3;
    int gidx = g * 128 + j;
    float s = b_ih[gidx] + b_hh[gidx];
    for (int k = 0; k < En; k++) s += rc[k] * g_WTrel[k * 512 + c];
    int q = c >> 2;
    int p = (q & ~31) | ((q & 1) << 4) | ((q & 31) >> 1);
    g_relGb[row * 512 + p * 4 + g] = s;
}

// ---------------- K3: entity gather + HMMA compress (2 CTA/SM) ----------------
#define SMC_A 0
#define SMC_B (128 * CKSTR)
#define SMC_TOTAL (2 * 128 * CKSTR)
__global__ __launch_bounds__(512, 2) void k_compress_mma(const int* __restrict__ paths,
                                                         const float* __restrict__ ent_table,
                                                         const float* __restrict__ ec_b) {
    extern __shared__ char sm[];
    __shared__ int spath[128];
    int tid = threadIdx.x, w = tid >> 5, l = tid & 31;
    int wm = w & 3, wn = w >> 2;
    int row0 = blockIdx.x * 128;

    if (tid < 128) spath[tid] = paths[row0 + tid];
    __syncthreads();
    for (int idx = tid; idx < 128 * 25; idx += 512) {
        int r = idx / 25, k4 = idx - r * 25;
        float4 v = *(const float4*)(ent_table + (size_t)spath[r] * DENT + k4 * 4);
        uint2 u;
        *((__half2*)&u.x) = __floats2half2_rn(v.x, v.y);
        *((__half2*)&u.y) = __floats2half2_rn(v.z, v.w);
        *(uint2*)(sm + SMC_A + r * CKSTR + k4 * 8) = u;
    }
    for (int idx = tid; idx < 128 * 3; idx += 512) {
        int r = idx / 3, j = idx - r * 3;
        *(uint2*)(sm + SMC_A + r * CKSTR + 200 + j * 8) = make_uint2(0u, 0u);
    }
    for (int idx = tid; idx < 128 * 28; idx += 512) {
        int r = idx / 28, j = idx - r * 28;
        *(uint2*)(sm + SMC_B + r * CKSTR + j * 8) = ((const uint2*)g_Wec)[idx];
    }
    __syncthreads();

    uint32_t base = s2u(sm);
    int g8 = l & 7;
    uint32_t aBase = base + SMC_A + (uint32_t)(wm * 32 + g8 + ((l >> 3) & 1) * 8) * CKSTR
                   + ((l >> 4) & 1) * 16;
    uint32_t bBase = base + SMC_B + (uint32_t)(wn * 32 + g8) * CKSTR + ((l >> 3) & 1) * 16;

    float acc[2][4][4];
#pragma unroll
    for (int mt = 0; mt < 2; mt++)
#pragma unroll
        for (int nt = 0; nt < 4; nt++)
#pragma unroll
            for (int q = 0; q < 4; q++) acc[mt][nt][q] = 0.0f;

#pragma unroll
    for (int kt = 0; kt < 7; kt++) {
        uint32_t a[2][4];
        ldmA(a[0], aBase + kt * 32);
        ldmA(a[1], aBase + 16 * CKSTR + kt * 32);
#pragma unroll
        for (int nt = 0; nt < 4; nt++) {
            uint32_t b[2];
            ldmB(b, bBase + nt * 8 * CKSTR + kt * 32);
            mma16816(acc[0][nt], a[0], b);
            mma16816(acc[1][nt], a[1], b);
        }
    }
    __syncthreads();

    int tg = l & 3, gg = l >> 2;
#pragma unroll
    for (int mt = 0; mt < 2; mt++) {
        int r = wm * 32 + mt * 16 + gg;
#pragma unroll
        for (int nt = 0; nt < 4; nt++) {
            int cc = wn * 32 + nt * 8 + 2 * tg;
            float b0 = __ldg(ec_b + cc), b1 = __ldg(ec_b + cc + 1);
            *(__half2*)(sm + r * ASTR + cc * 2) =
                __floats2half2_rn(tanha(acc[mt][nt][0] + b0), tanha(acc[mt][nt][1] + b1));
            *(__half2*)(sm + (r + 8) * ASTR + cc * 2) =
                __floats2half2_rn(tanha(acc[mt][nt][2] + b0), tanha(acc[mt][nt][3] + b1));
        }
    }
    __syncthreads();
    for (int it = tid; it < 128 * 16; it += 512) {
        int r = it >> 4, bb = it & 15;
        uint4 v = *(uint4*)(sm + r * ASTR + bb * 16);
        *(uint4*)((char*)g_AE + (size_t)(row0 + r) * 256 + bb * 16) = v;
    }
}

// ---------------- K4: HMMA GEMM, A staged once, N looped in 4 chunks, 2 CTA/SM -----------
#define SMG_A 0
#define SMG_B (128 * ASTR)
#define SMG_TOTAL (2 * 128 * ASTR)        /* 69632 */
__global__ __launch_bounds__(512, 2) void k_gemm_mma() {
    extern __shared__ char sm[];
    int tid = threadIdx.x, w = tid >> 5, l = tid & 31;
    int wm = w & 3, wn = w >> 2;
    int row0 = blockIdx.x * 128;

    const uint4* Ag = (const uint4*)g_AE;
    for (int idx = tid; idx < 128 * 16; idx += 512) {
        int r = idx >> 4, c4 = idx & 15;
        *(uint4*)(sm + SMG_A + r * ASTR + c4 * 16) = Ag[(size_t)(row0 + r) * 16 + c4];
    }

    uint32_t base = s2u(sm);
    int g8 = l & 7, tg = l & 3, gg = l >> 2;
    uint32_t aBase = base + SMG_A + (uint32_t)(wm * 32 + g8 + ((l >> 3) & 1) * 8) * ASTR
                   + ((l >> 4) & 1) * 16;
    uint32_t bBase = base + SMG_B + (uint32_t)(wn * 32 + g8) * ASTR + ((l >> 3) & 1) * 16;
    const uint4* Bg = (const uint4*)g_Bn;

    for (int nc = 0; nc < 4; nc++) {
        __syncthreads();    // prior streamout reads done (nc=0: A staging visible)
        for (int idx = tid; idx < 128 * 16; idx += 512) {
            int n = idx >> 4, c4 = idx & 15;
            *(uint4*)(sm + SMG_B + n * ASTR + c4 * 16) = Bg[(size_t)(nc * 128 + n) * 16 + c4];
        }
        __syncthreads();

        float acc[2][4][4];
#pragma unroll
        for (int mt = 0; mt < 2; mt++)
#pragma unroll
            for (int nt = 0; nt < 4; nt++)
#pragma unroll
                for (int q = 0; q < 4; q++) acc[mt][nt][q] = 0.0f;

#pragma unroll
        for (int kt = 0; kt < 8; kt++) {
            uint32_t a[2][4];
            ldmA(a[0], aBase + kt * 32);
            ldmA(a[1], aBase + 16 * ASTR + kt * 32);
#pragma unroll
            for (int nt = 0; nt < 4; nt++) {
                uint32_t b[2];
                ldmB(b, bBase + nt * 8 * ASTR + kt * 32);
                mma16816(acc[0][nt], a[0], b);
                mma16816(acc[1][nt], a[1], b);
            }
        }
        __syncthreads();    // B reads done; overlay C staging on B region

#pragma unroll
        for (int mt = 0; mt < 2; mt++) {
            int r = wm * 32 + mt * 16 + gg;
#pragma unroll
            for (int nt = 0; nt < 4; nt++) {
                int qg = wn * 8 + nt * 2 + (tg >> 1);             // local quad 0..31
                int pl = ((qg & 1) << 4) | (qg >> 1);
                *(__half2*)(sm + SMG_B + r * ASTR + pl * 8 + (tg & 1) * 4) =
                    __floats2half2_rn(acc[mt][nt][0], acc[mt][nt][1]);
                *(__half2*)(sm + SMG_B + (r + 8) * ASTR + pl * 8 + (tg & 1) * 4) =
                    __floats2half2_rn(acc[mt][nt][2], acc[mt][nt][3]);
            }
        }
        __syncthreads();
        for (int it = tid; it < 128 * 16; it += 512) {
            int r = it >> 4, bb = it & 15;
            uint4 v = *(uint4*)(sm + SMG_B + r * ASTR + bb * 16);
            *(uint4*)((char*)g_G16 + (size_t)(row0 + r) * 1024 + nc * 256 + bb * 16) = v;
        }
    }
}

// ---------------- K5: HMMA LSTM + fused MLP (halves, upfront gate prefetch) -------------
#define SML_A0 0
#define SML_A1 (64 * ASTR)
#define SML_B  (2 * 64 * ASTR)
#define SML_W1 SML_B
#define SML_PART (SML_B + 512 * ASTR)
#define SML_TOTAL (SML_PART + 2048)
__global__ __launch_bounds__(512, 1) void k_lstm_mma(const int* __restrict__ edges,
                                                     const float* __restrict__ mlp_W1,
                                                     const float* __restrict__ mlp_b1,
                                                     const float* __restrict__ mlp_W2,
                                                     const float* __restrict__ mlp_b2,
                                                     float* __restrict__ scores_out) {
    extern __shared__ char sm[];
    int tid = threadIdx.x, w = tid >> 5, l = tid & 31;
    int wm = w & 3, wn = w >> 2;
    int n0 = blockIdx.x * 64;
    int g8 = l & 7, tg = l & 3, gg = l >> 2;
    int odd = tg & 1;
    int par = tg >> 1;

    int r_loc = wm * 16 + gg + odd * 8;
    int seq = n0 + r_loc;
    int bIdx = seq / Pn;

    // prefetch t=0 gate stream while staging B (hides DRAM latency under 131KB staging)
    const uint4* gp0 = (const uint4*)((const char*)g_G16 + (size_t)(NPL + bIdx) * 1024
                                      + (size_t)(wn * 32 + par * 16) * 8);
    uint4 gu[8];
#pragma unroll
    for (int k2 = 0; k2 < 8; k2++) gu[k2] = gp0[k2];

    const uint4* Bg = (const uint4*)g_Bh;
    for (int idx = tid; idx < 512 * 16; idx += 512) {
        int n = idx >> 4, c4 = idx & 15;
        *(uint4*)(sm + SML_B + n * ASTR + c4 * 16) = Bg[(size_t)n * 16 + c4];
    }
    __syncthreads();

    uint32_t base = s2u(sm);
    uint32_t aLane = (uint32_t)(wm * 16 + g8 + ((l >> 3) & 1) * 8) * ASTR + ((l >> 4) & 1) * 16;
    uint32_t bBase = base + SML_B + (uint32_t)(wn * 128 + g8) * ASTR + ((l >> 3) & 1) * 16;

    float cst[16];
#pragma unroll
    for (int q = 0; q < 16; q++) cst[q] = 0.0f;

    for (int t = 0; t < Tn; t++) {
        uint32_t aRd = base + ((t & 1) ? SML_A0 : SML_A1) + aLane;
        char* hWr = sm + ((t & 1) ? SML_A1 : SML_A0);
        int e = (t < Ln) ? edges[seq * Ln + t] : 0;
        const float4* rp = (const float4*)(g_relGb + (size_t)e * 512
                                           + (wn * 32 + par * 16) * 4);

#pragma unroll
        for (int half = 0; half < 2; half++) {
            float acc[8][4];
#pragma unroll
            for (int nt = 0; nt < 8; nt++)
#pragma unroll
                for (int q = 0; q < 4; q++) acc[nt][q] = 0.0f;
            if (t > 0) {
#pragma unroll
                for (int kt = 0; kt < 8; kt++) {
                    uint32_t a[4];
                    ldmA(a, aRd + kt * 32);
#pragma unroll
                    for (int ntl = 0; ntl < 8; ntl++) {
                        uint32_t b[2];
                        ldmB(b, bBase + (half * 8 + ntl) * 8 * ASTR + kt * 32);
                        mma16816(acc[ntl], a, b);
                    }
                }
            }
#pragma unroll
            for (int ntl = 0; ntl < 8; ntl++) {
                int nt = half * 8 + ntl;
                float d0 = acc[ntl][0], d1 = acc[ntl][1];
                float d2 = acc[ntl][2], d3 = acc[ntl][3];
                float x0 = __shfl_xor_sync(0xffffffffu, d0, 1);
                float x1 = __shfl_xor_sync(0xffffffffu, d1, 1);
                float x2 = __shfl_xor_sync(0xffffffffu, d2, 1);
                float x3 = __shfl_xor_sync(0xffffffffu, d3, 1);
                float gi = odd ? x2 : d0;
                float gf = odd ? x3 : d1;
                float gG = odd ? d2 : x0;
                float gO = odd ? d3 : x1;
                __half2 hif = ((const __half2*)&gu[half * 4 + (ntl >> 1)])[(ntl & 1) * 2 + 0];
                __half2 hgo = ((const __half2*)&gu[half * 4 + (ntl >> 1)])[(ntl & 1) * 2 + 1];
                float2 fif = __half22float2(hif);
                float2 fgo = __half22float2(hgo);
                float4 r4 = rp[nt];
                gi += fif.x + r4.x;
                gf += fif.y + r4.y;
                gG += fgo.x + r4.z;
                gO += fgo.y + r4.w;
                cst[nt] = siga(gf) * cst[nt] + siga(gi) * tanha(gG);
                float hv = siga(gO) * tanha(cst[nt]);
                int q = wn * 32 + nt * 2 + par;
                *(__half*)(hWr + r_loc * ASTR + q * 2) = __float2half_rn(hv);
            }
        }
        // prefetch next step's gate stream (independent of the barrier below)
        if (t + 1 < Tn) {
            int rowG = (t + 1 == 4) ? NPL + Bsz + bIdx : seq * Ln + t;
            const uint4* gp = (const uint4*)((const char*)g_G16 + (size_t)rowG * 1024
                                             + (size_t)(wn * 32 + par * 16) * 8);
#pragma unroll
            for (int k2 = 0; k2 < 8; k2++) gu[k2] = gp[k2];
        }
        __syncthreads();
    }

    // ---- fused MLP: final h in buffer A0 ----
    float* sW1 = (float*)(sm + SML_W1);
    for (int idx = tid; idx < 128 * 128; idx += 512) sW1[idx] = mlp_W1[idx];
    __syncthreads();

    int m = tid & 63, jb = (tid >> 6) * 16;
    u64 m1[8];
#pragma unroll
    for (int p = 0; p < 8; p++) m1[p] = pack2(mlp_b1[jb + 2 * p], mlp_b1[jb + 2 * p + 1]);
    const __half* hrow = (const __half*)(sm + SML_A0 + m * ASTR);
#pragma unroll 4
    for (int k = 0; k < 128; k++) {
        u64 hd = dup2(__half2float(hrow[k]));
        const u64* wp = (const u64*)&sW1[k * 128 + jb];
#pragma unroll
        for (int p = 0; p < 8; p++) m1[p] = ffma2(wp[p], hd, m1[p]);
    }
    float v = 0.0f;
#pragma unroll
    for (int p = 0; p < 8; p++) {
        float2 a = up2(m1[p]);
        v += fmaxf(a.x, 0.0f) * mlp_W2[jb + 2 * p]
           + fmaxf(a.y, 0.0f) * mlp_W2[jb + 2 * p + 1];
    }
    float* part = (float*)(sm + SML_PART);
    part[m * 8 + (tid >> 6)] = v;
    __syncthreads();
    if (tid < 64) {
        float s = mlp_b2[0];
#pragma unroll
        for (int p = 0; p < 8; p++) s += part[tid * 8 + p];
        scores_out[n0 + tid] = s;
    }
}

// ---------------- K7: logsumexp + BCE ----------------
__global__ void k_final(const float* __restrict__ label, float* __restrict__ out) {
    __shared__ float red[Bsz];
    int b = threadIdx.x;
    const float* sc = out + 1 + Bsz + b * Pn;
    float mx = -1e30f;
#pragma unroll
    for (int p = 0; p < Pn; p++) mx = fmaxf(mx, sc[p] * 0.5f);
    float s = 0.0f;
#pragma unroll
    for (int p = 0; p < Pn; p++) s += expf(sc[p] * 0.5f - mx);
    float lse = mx + logf(s);
    float pr = 1.0f / (1.0f + expf(-lse));
    out[1 + b] = pr;
    float pc = fminf(fmaxf(pr, 1e-7f), 1.0f - 1e-7f);
    float lb = label[b];
    red[b] = -(lb * logf(pc) + (1.0f - lb) * logf(1.0f - pc));
    __syncthreads();
    for (int st = Bsz / 2; st > 0; st >>= 1) {
        if (b < st) red[b] += red[b + st];
        __syncthreads();
    }
    if (b == 0) out[0] = red[0] / (float)Bsz;
}

// ---------------- launch ----------------
extern "C" void kernel_launch(void* const* d_in, const int* in_sizes, int n_in,
                              void* d_out, int out_size) {
    const int*   item1     = (const int*)d_in[0];
    const int*   item2     = (const int*)d_in[1];
    const int*   paths     = (const int*)d_in[2];
    const int*   edges     = (const int*)d_in[3];
    const float* label     = (const float*)d_in[4];
    const float* doc_table = (const float*)d_in[5];
    const float* ent_table = (const float*)d_in[6];
    const float* rel_table = (const float*)d_in[7];
    const float* nc_W1 = (const float*)d_in[8];
    const float* nc_b1 = (const float*)d_in[9];
    const float* nc_W2 = (const float*)d_in[10];
    const float* nc_b2 = (const float*)d_in[11];
    const float* ec_W  = (const float*)d_in[12];
    const float* ec_b  = (const float*)d_in[13];
    const float* rc_W  = (const float*)d_in[14];
    const float* rc_b  = (const float*)d_in[15];
    const float* W_ih  = (const float*)d_in[16];
    const float* W_hh  = (const float*)d_in[17];
    const float* b_ih  = (const float*)d_in[18];
    const float* b_hh  = (const float*)d_in[19];
    const float* mlp_W1 = (const float*)d_in[20];
    const float* mlp_b1 = (const float*)d_in[21];
    const float* mlp_W2 = (const float*)d_in[22];
    const float* mlp_b2 = (const float*)d_in[23];
    float* out = (float*)d_out;

    cudaFuncSetAttribute(k_compress_mma, cudaFuncAttributeMaxDynamicSharedMemorySize, SMC_TOTAL);
    cudaFuncSetAttribute(k_gemm_mma, cudaFuncAttributeMaxDynamicSharedMemorySize, SMG_TOTAL);
    cudaFuncSetAttribute(k_lstm_mma, cudaFuncAttributeMaxDynamicSharedMemorySize, SML_TOTAL);

    k_transpose<<<(512 * 128 + 511) / 512, 512>>>(W_ih, W_hh, ec_W);
    k_news<<<2 * Bsz / 8, 128>>>(item1, item2, doc_table, nc_W1, nc_b1, nc_W2, nc_b2);
    k_rel<<<NREL, 512>>>(rel_table, rc_W, rc_b, b_ih, b_hh);
    k_compress_mma<<<NPL / 128, 512, SMC_TOTAL>>>(paths, ent_table, ec_b);
    k_gemm_mma<<<MTOT / 128, 512, SMG_TOTAL>>>();
    k_lstm_mma<<<Nseq / 64, 512, SML_TOTAL>>>(edges, mlp_W1, mlp_b1, mlp_W2, mlp_b2,
                                              out + 1 + Bsz);
    k_final<<<1, Bsz>>>(label, out);
}

// round 10
// speedup vs baseline: 1.2553x; 1.0690x over previous
#include <cuda_runtime.h>
#include <cuda_fp16.h>
#include <math.h>
#include <stdint.h>

typedef unsigned long long u64;

#define Bsz   1024
#define Pn    20
#define Ln    3
#define Tn    5
#define En    128
#define Nseq  (Bsz*Pn)          /* 20480 */
#define NPL   (Bsz*Pn*Ln)       /* 61440 */
#define NREL  60
#define DDOC  768
#define DENT  100
#define KPAD  112
#define MTOT  (NPL + 2*Bsz)     /* 63488 = 496*128 */

// ---------------- device scratch ----------------
__device__ __half g_AE [(size_t)MTOT * 128];
__device__ __half g_Bn [512 * 128];             // W_ih[:,0:128], rows in c' gate-pair order
__device__ __half g_Bh [512 * 128];             // W_hh, rows in c' gate-pair order
__device__ __half g_Wec[128 * KPAD];
__device__ float  g_WTrel[128 * 512];           // f32 [k][c']
__device__ float  g_relGb[NREL * 512];          // per-thread-contiguous gate layout
__device__ __half g_G16 [(size_t)MTOT * 512];   // per-thread-contiguous gate layout

// c' mapping: u=c'>>4, half=(c'>>3)&1, t=(c'>>1)&3, gb=c'&1 -> j=u*4+t, gate=half*2+gb
// storage pos(j,gate) = (j>>5)*128 + (j&3)*32 + ((j>>2)&7)*4 + gate

// ---- fast transcendentals ----
__device__ __forceinline__ float tanha(float x) {
    float y; asm("tanh.approx.f32 %0, %1;" : "=f"(y) : "f"(x)); return y;
}
__device__ __forceinline__ float siga(float x) {
    return fmaf(tanha(x * 0.5f), 0.5f, 0.5f);
}

// ---- f32x2 helpers ----
__device__ __forceinline__ u64 ffma2(u64 a, u64 b, u64 c) {
    u64 d; asm("fma.rn.f32x2 %0, %1, %2, %3;" : "=l"(d) : "l"(a), "l"(b), "l"(c)); return d;
}
__device__ __forceinline__ u64 dup2(float x) {
    u64 d; unsigned xi = __float_as_uint(x);
    asm("mov.b64 %0, {%1, %1};" : "=l"(d) : "r"(xi)); return d;
}
__device__ __forceinline__ u64 pack2(float lo, float hi) {
    u64 d; asm("mov.b64 %0, {%1, %2};" : "=l"(d) : "r"(__float_as_uint(lo)), "r"(__float_as_uint(hi)));
    return d;
}
__device__ __forceinline__ float2 up2(u64 v) {
    unsigned lo, hi; asm("mov.b64 {%0, %1}, %2;" : "=r"(lo), "=r"(hi) : "l"(v));
    return make_float2(__uint_as_float(lo), __uint_as_float(hi));
}

// ---- mma / ldmatrix ----
__device__ __forceinline__ uint32_t s2u(const void* p) {
    uint32_t a;
    asm("{ .reg .u64 t; cvta.to.shared.u64 t, %1; cvt.u32.u64 %0, t; }" : "=r"(a) : "l"(p));
    return a;
}
__device__ __forceinline__ void ldmA(uint32_t* r, uint32_t addr) {
    asm volatile("ldmatrix.sync.aligned.m8n8.x4.shared.b16 {%0,%1,%2,%3}, [%4];"
                 : "=r"(r[0]), "=r"(r[1]), "=r"(r[2]), "=r"(r[3]) : "r"(addr));
}
__device__ __forceinline__ void ldmB(uint32_t* r, uint32_t addr) {
    asm volatile("ldmatrix.sync.aligned.m8n8.x2.shared.b16 {%0,%1}, [%2];"
                 : "=r"(r[0]), "=r"(r[1]) : "r"(addr));
}
__device__ __forceinline__ void mma16816(float* d, const uint32_t* a, const uint32_t* b) {
    asm volatile("mma.sync.aligned.m16n8k16.row.col.f32.f16.f16.f32 "
        "{%0,%1,%2,%3}, {%4,%5,%6,%7}, {%8,%9}, {%0,%1,%2,%3};"
        : "+f"(d[0]), "+f"(d[1]), "+f"(d[2]), "+f"(d[3])
        : "r"(a[0]), "r"(a[1]), "r"(a[2]), "r"(a[3]), "r"(b[0]), "r"(b[1]));
}

#define ASTR  272
#define CKSTR 240
#define DSTR  10

// ---------------- L0: news (blocks 0..255) + weight transpose (blocks 256..767) ----------
__global__ void k_news_transpose(const int* __restrict__ item1, const int* __restrict__ item2,
                                 const float* __restrict__ doc_table,
                                 const float* __restrict__ W1, const float* __restrict__ b1,
                                 const float* __restrict__ W2, const float* __restrict__ b2,
                                 const float* __restrict__ W_ih, const float* __restrict__ W_hh,
                                 const float* __restrict__ ec_W) {
    __shared__ __align__(16) float dsp[DDOC * DSTR];
    __shared__ __align__(16) float h1p[En * DSTR];
    __shared__ int items[8];
    int tid = threadIdx.x;

    if (blockIdx.x >= 256) {
        // ---- transpose / pack role ----
        int idx = (blockIdx.x - 256) * 128 + tid;
        if (idx < 128 * KPAD) {
            int c = idx / KPAD, k = idx - c * KPAD;
            g_Wec[idx] = (k < DENT) ? __float2half_rn(ec_W[k * 128 + c]) : __half(0.0f);
        }
        int c = idx >> 7, k = idx & 127;
        int u = c >> 4, half = (c >> 3) & 1, t = (c >> 1) & 3, gb = c & 1;
        int j = u * 4 + t, gate = half * 2 + gb;
        int row = gate * 128 + j;
        g_Bn[c * 128 + k] = __float2half_rn(W_ih[row * 256 + k]);
        g_Bh[c * 128 + k] = __float2half_rn(W_hh[row * 128 + k]);
        g_WTrel[k * 512 + c] = W_ih[row * 256 + 128 + k];
        return;
    }

    // ---- news role ----
    int r0 = blockIdx.x * 8;
    if (tid < 8) {
        int row = r0 + tid;
        items[tid] = (row < Bsz) ? item1[row] : item2[row - Bsz];
    }
    __syncthreads();
    for (int k = tid; k < DDOC; k += 128) {
#pragma unroll
        for (int r = 0; r < 8; r++)
            dsp[k * DSTR + r] = doc_table[(size_t)items[r] * DDOC + k];
    }
    __syncthreads();
    u64 acc2[4];
    u64 bd = dup2(b1[tid]);
#pragma unroll
    for (int p = 0; p < 4; p++) acc2[p] = bd;
    for (int k = 0; k < DDOC; k++) {
        u64 wd = dup2(W1[k * En + tid]);
        const u64* hp = (const u64*)&dsp[k * DSTR];
#pragma unroll
        for (int p = 0; p < 4; p++) acc2[p] = ffma2(hp[p], wd, acc2[p]);
    }
#pragma unroll
    for (int p = 0; p < 4; p++) {
        float2 a = up2(acc2[p]);
        h1p[tid * DSTR + 2 * p]     = (a.x > 0.0f) ? a.x : expm1f(a.x);
        h1p[tid * DSTR + 2 * p + 1] = (a.y > 0.0f) ? a.y : expm1f(a.y);
    }
    __syncthreads();
    u64 bd2 = dup2(b2[tid]);
#pragma unroll
    for (int p = 0; p < 4; p++) acc2[p] = bd2;
    for (int k = 0; k < En; k++) {
        u64 wd = dup2(W2[k * En + tid]);
        const u64* hp = (const u64*)&h1p[k * DSTR];
#pragma unroll
        for (int p = 0; p < 4; p++) acc2[p] = ffma2(hp[p], wd, acc2[p]);
    }
#pragma unroll
    for (int p = 0; p < 4; p++) {
        float2 a = up2(acc2[p]);
        g_AE[(size_t)(NPL + r0 + 2 * p)     * En + tid] = __float2half_rn(tanhf(a.x));
        g_AE[(size_t)(NPL + r0 + 2 * p + 1) * En + tid] = __float2half_rn(tanhf(a.y));
    }
}

// ---------------- L1: entity compress (blocks 0..479) + relations (480..539) --------------
#define SMC_A 0
#define SMC_B (128 * CKSTR)
#define SMC_TOTAL (2 * 128 * CKSTR)
__global__ __launch_bounds__(512, 2) void k_compress_rel(const int* __restrict__ paths,
                                                         const float* __restrict__ ent_table,
                                                         const float* __restrict__ ec_b,
                                                         const float* __restrict__ rel_table,
                                                         const float* __restrict__ rc_W,
                                                         const float* __restrict__ rc_b,
                                                         const float* __restrict__ b_ih,
                                                         const float* __restrict__ b_hh) {
    extern __shared__ char sm[];
    __shared__ int spath[128];
    __shared__ float rr[DENT];
    __shared__ float rcs[En];
    int tid = threadIdx.x;

    if (blockIdx.x >= NPL / 128) {
        // ---- relation role ----
        int rrow = blockIdx.x - NPL / 128;
        if (tid < DENT) rr[tid] = rel_table[rrow * DENT + tid];
        __syncthreads();
        if (tid < En) {
            float s = rc_b[tid];
            for (int k = 0; k < DENT; k++) s += rr[k] * rc_W[k * En + tid];
            rcs[tid] = tanhf(s);
        }
        __syncthreads();
        int c = tid;
        int u = c >> 4, half = (c >> 3) & 1, t = (c >> 1) & 3, gb = c & 1;
        int j = u * 4 + t, gate = half * 2 + gb;
        int gidx = gate * 128 + j;
        float s = b_ih[gidx] + b_hh[gidx];
        for (int k = 0; k < En; k++) s += rcs[k] * g_WTrel[k * 512 + c];
        int pos = (j >> 5) * 128 + (j & 3) * 32 + ((j >> 2) & 7) * 4 + gate;
        g_relGb[rrow * 512 + pos] = s;
        return;
    }

    // ---- compress role ----
    int w = tid >> 5, l = tid & 31;
    int wm = w & 3, wn = w >> 2;
    int row0 = blockIdx.x * 128;

    if (tid < 128) spath[tid] = paths[row0 + tid];
    __syncthreads();
    for (int idx = tid; idx < 128 * 25; idx += 512) {
        int r = idx / 25, k4 = idx - r * 25;
        float4 v = *(const float4*)(ent_table + (size_t)spath[r] * DENT + k4 * 4);
        uint2 u2;
        *((__half2*)&u2.x) = __floats2half2_rn(v.x, v.y);
        *((__half2*)&u2.y) = __floats2half2_rn(v.z, v.w);
        *(uint2*)(sm + SMC_A + r * CKSTR + k4 * 8) = u2;
    }
    for (int idx = tid; idx < 128 * 3; idx += 512) {
        int r = idx / 3, j = idx - r * 3;
        *(uint2*)(sm + SMC_A + r * CKSTR + 200 + j * 8) = make_uint2(0u, 0u);
    }
    for (int idx = tid; idx < 128 * 28; idx += 512) {
        int r = idx / 28, j = idx - r * 28;
        *(uint2*)(sm + SMC_B + r * CKSTR + j * 8) = ((const uint2*)g_Wec)[idx];
    }
    __syncthreads();

    uint32_t base = s2u(sm);
    int g8 = l & 7;
    uint32_t aBase = base + SMC_A + (uint32_t)(wm * 32 + g8 + ((l >> 3) & 1) * 8) * CKSTR
                   + ((l >> 4) & 1) * 16;
    uint32_t bBase = base + SMC_B + (uint32_t)(wn * 32 + g8) * CKSTR + ((l >> 3) & 1) * 16;

    float acc[2][4][4];
#pragma unroll
    for (int mt = 0; mt < 2; mt++)
#pragma unroll
        for (int nt = 0; nt < 4; nt++)
#pragma unroll
            for (int q = 0; q < 4; q++) acc[mt][nt][q] = 0.0f;

#pragma unroll
    for (int kt = 0; kt < 7; kt++) {
        uint32_t a[2][4];
        ldmA(a[0], aBase + kt * 32);
        ldmA(a[1], aBase + 16 * CKSTR + kt * 32);
#pragma unroll
        for (int nt = 0; nt < 4; nt++) {
            uint32_t b[2];
            ldmB(b, bBase + nt * 8 * CKSTR + kt * 32);
            mma16816(acc[0][nt], a[0], b);
            mma16816(acc[1][nt], a[1], b);
        }
    }
    __syncthreads();

    int tg = l & 3, gg = l >> 2;
#pragma unroll
    for (int mt = 0; mt < 2; mt++) {
        int r = wm * 32 + mt * 16 + gg;
#pragma unroll
        for (int nt = 0; nt < 4; nt++) {
            int cc = wn * 32 + nt * 8 + 2 * tg;
            float b0 = __ldg(ec_b + cc), b1 = __ldg(ec_b + cc + 1);
            *(__half2*)(sm + r * ASTR + cc * 2) =
                __floats2half2_rn(tanha(acc[mt][nt][0] + b0), tanha(acc[mt][nt][1] + b1));
            *(__half2*)(sm + (r + 8) * ASTR + cc * 2) =
                __floats2half2_rn(tanha(acc[mt][nt][2] + b0), tanha(acc[mt][nt][3] + b1));
        }
    }
    __syncthreads();
    for (int it = tid; it < 128 * 16; it += 512) {
        int r = it >> 4, bb = it & 15;
        uint4 v = *(uint4*)(sm + r * ASTR + bb * 16);
        *(uint4*)((char*)g_AE + (size_t)(row0 + r) * 256 + bb * 16) = v;
    }
}

// ---------------- L2: HMMA gate GEMM, A staged once, 4 N-chunks, 2 CTA/SM ----------------
#define SMG_A 0
#define SMG_B (128 * ASTR)
#define SMG_TOTAL (2 * 128 * ASTR)        /* 69632 */
__global__ __launch_bounds__(512, 2) void k_gemm_mma() {
    extern __shared__ char sm[];
    int tid = threadIdx.x, w = tid >> 5, l = tid & 31;
    int wm = w & 3, wn = w >> 2;
    int row0 = blockIdx.x * 128;

    const uint4* Ag = (const uint4*)g_AE;
    for (int idx = tid; idx < 128 * 16; idx += 512) {
        int r = idx >> 4, c4 = idx & 15;
        *(uint4*)(sm + SMG_A + r * ASTR + c4 * 16) = Ag[(size_t)(row0 + r) * 16 + c4];
    }

    uint32_t base = s2u(sm);
    int g8 = l & 7, tg = l & 3, gg = l >> 2;
    uint32_t aBase = base + SMG_A + (uint32_t)(wm * 32 + g8 + ((l >> 3) & 1) * 8) * ASTR
                   + ((l >> 4) & 1) * 16;
    uint32_t bBase = base + SMG_B + (uint32_t)(wn * 32 + g8) * ASTR + ((l >> 3) & 1) * 16;
    const uint4* Bg = (const uint4*)g_Bn;

    for (int nc = 0; nc < 4; nc++) {
        __syncthreads();
        for (int idx = tid; idx < 128 * 16; idx += 512) {
            int n = idx >> 4, c4 = idx & 15;
            *(uint4*)(sm + SMG_B + n * ASTR + c4 * 16) = Bg[(size_t)(nc * 128 + n) * 16 + c4];
        }
        __syncthreads();

        float acc[2][4][4];
#pragma unroll
        for (int mt = 0; mt < 2; mt++)
#pragma unroll
            for (int nt = 0; nt < 4; nt++)
#pragma unroll
                for (int q = 0; q < 4; q++) acc[mt][nt][q] = 0.0f;

#pragma unroll
        for (int kt = 0; kt < 8; kt++) {
            uint32_t a[2][4];
            ldmA(a[0], aBase + kt * 32);
            ldmA(a[1], aBase + 16 * ASTR + kt * 32);
#pragma unroll
            for (int nt = 0; nt < 4; nt++) {
                uint32_t b[2];
                ldmB(b, bBase + nt * 8 * ASTR + kt * 32);
                mma16816(acc[0][nt], a[0], b);
                mma16816(acc[1][nt], a[1], b);
            }
        }
        __syncthreads();   // B reads done; overlay C staging

        // stage C in per-thread-contiguous gate layout (local f16 idx within 256B chunk)
#pragma unroll
        for (int mt = 0; mt < 2; mt++) {
            int r = wm * 32 + mt * 16 + gg;
#pragma unroll
            for (int nt = 0; nt < 4; nt++) {
                int pos2b = tg * 64 + (wn * 2 + (nt >> 1)) * 8 + (nt & 1) * 4;
                *(__half2*)(sm + SMG_B + r * ASTR + pos2b) =
                    __floats2half2_rn(acc[mt][nt][0], acc[mt][nt][1]);
                *(__half2*)(sm + SMG_B + (r + 8) * ASTR + pos2b) =
                    __floats2half2_rn(acc[mt][nt][2], acc[mt][nt][3]);
            }
        }
        __syncthreads();
        for (int it = tid; it < 128 * 16; it += 512) {
            int r = it >> 4, bb = it & 15;
            uint4 v = *(uint4*)(sm + SMG_B + r * ASTR + bb * 16);
            *(uint4*)((char*)g_G16 + (size_t)(row0 + r) * 1024 + nc * 256 + bb * 16) = v;
        }
    }
}

// ---------------- L3: HMMA LSTM + fused MLP (no shuffles, quarter chunks) ----------------
#define SML_A0 0
#define SML_A1 (64 * ASTR)
#define SML_B  (2 * 64 * ASTR)
#define SML_W1 SML_B
#define SML_PART (SML_B + 512 * ASTR)
#define SML_TOTAL (SML_PART + 2048)
__global__ __launch_bounds__(512, 1) void k_lstm_mma(const int* __restrict__ edges,
                                                     const float* __restrict__ mlp_W1,
                                                     const float* __restrict__ mlp_b1,
                                                     const float* __restrict__ mlp_W2,
                                                     const float* __restrict__ mlp_b2,
                                                     float* __restrict__ scores_out) {
    extern __shared__ char sm[];
    int tid = threadIdx.x, w = tid >> 5, l = tid & 31;
    int wm = w & 3, wn = w >> 2;
    int n0 = blockIdx.x * 64;
    int g8 = l & 7, t4 = l & 3, gg = l >> 2;

    const uint4* Bg = (const uint4*)g_Bh;
    for (int idx = tid; idx < 512 * 16; idx += 512) {
        int n = idx >> 4, c4 = idx & 15;
        *(uint4*)(sm + SML_B + n * ASTR + c4 * 16) = Bg[(size_t)n * 16 + c4];
    }
    __syncthreads();

    uint32_t base = s2u(sm);
    uint32_t aLane = (uint32_t)(wm * 16 + g8 + ((l >> 3) & 1) * 8) * ASTR + ((l >> 4) & 1) * 16;
    uint32_t bBase = base + SML_B + (uint32_t)(wn * 128 + g8) * ASTR + ((l >> 3) & 1) * 16;

    int rowA = wm * 16 + gg;              // thread's two rows: rowA, rowA+8
    int seqA = n0 + rowA, seqB = seqA + 8;
    int bA = seqA / Pn, bB = seqB / Pn;
    int goff = wn * 256 + t4 * 64;        // byte offset of this thread's gate stream
    int roff = wn * 128 + t4 * 32;        // float offset in relGb rows

    float cst[16];                        // [u_local*2 + rowbit]
#pragma unroll
    for (int q = 0; q < 16; q++) cst[q] = 0.0f;

    for (int t = 0; t < Tn; t++) {
        uint32_t aRd = base + ((t & 1) ? SML_A0 : SML_A1) + aLane;
        char* hWr = sm + ((t & 1) ? SML_A1 : SML_A0);
        int rowGA = (t == 0) ? NPL + bA : (t == 4) ? NPL + Bsz + bA : seqA * Ln + (t - 1);
        int rowGB = (t == 0) ? NPL + bB : (t == 4) ? NPL + Bsz + bB : seqB * Ln + (t - 1);
        int eA = (t < Ln) ? edges[seqA * Ln + t] : 0;
        int eB = (t < Ln) ? edges[seqB * Ln + t] : 0;
        const char* gA = (const char*)g_G16 + (size_t)rowGA * 1024 + goff;
        const char* gB = (const char*)g_G16 + (size_t)rowGB * 1024 + goff;
        const float* rA = g_relGb + (size_t)eA * 512 + roff;
        const float* rB = g_relGb + (size_t)eB * 512 + roff;

#pragma unroll
        for (int qc = 0; qc < 4; qc++) {
            // issue gate + rel loads first (hidden under the mma below)
            uint4 guA = *(const uint4*)(gA + qc * 16);
            uint4 guB = *(const uint4*)(gB + qc * 16);
            float4 rA0 = *(const float4*)(rA + qc * 8);
            float4 rA1 = *(const float4*)(rA + qc * 8 + 4);
            float4 rB0 = *(const float4*)(rB + qc * 8);
            float4 rB1 = *(const float4*)(rB + qc * 8 + 4);

            float acc[4][4];
#pragma unroll
            for (int ni = 0; ni < 4; ni++)
#pragma unroll
                for (int q = 0; q < 4; q++) acc[ni][q] = 0.0f;
            if (t > 0) {
#pragma unroll
                for (int kt = 0; kt < 8; kt++) {
                    uint32_t a[4];
                    ldmA(a, aRd + kt * 32);
#pragma unroll
                    for (int ni = 0; ni < 4; ni++) {
                        uint32_t b[2];
                        ldmB(b, bBase + (qc * 4 + ni) * 8 * ASTR + kt * 32);
                        mma16816(acc[ni], a, b);
                    }
                }
            }
#pragma unroll
            for (int p = 0; p < 2; p++) {
                int ul = qc * 2 + p;
                float2 fifA = __half22float2(((const __half2*)&guA)[p * 2 + 0]);
                float2 fgoA = __half22float2(((const __half2*)&guA)[p * 2 + 1]);
                float2 fifB = __half22float2(((const __half2*)&guB)[p * 2 + 0]);
                float2 fgoB = __half22float2(((const __half2*)&guB)[p * 2 + 1]);
                float4 ra = p ? rA1 : rA0;
                float4 rb = p ? rB1 : rB0;
                // row A (gg): acc[2p][0..1] = (i,f), acc[2p+1][0..1] = (g,o)
                float gi = acc[2 * p][0] + fifA.x + ra.x;
                float gf = acc[2 * p][1] + fifA.y + ra.y;
                float gG = acc[2 * p + 1][0] + fgoA.x + ra.z;
                float gO = acc[2 * p + 1][1] + fgoA.y + ra.w;
                int ci = ul * 2;
                cst[ci] = siga(gf) * cst[ci] + siga(gi) * tanha(gG);
                float hA = siga(gO) * tanha(cst[ci]);
                // row B (gg+8): acc[..][2..3]
                gi = acc[2 * p][2] + fifB.x + rb.x;
                gf = acc[2 * p][3] + fifB.y + rb.y;
                gG = acc[2 * p + 1][2] + fgoB.x + rb.z;
                gO = acc[2 * p + 1][3] + fgoB.y + rb.w;
                cst[ci + 1] = siga(gf) * cst[ci + 1] + siga(gi) * tanha(gG);
                float hB = siga(gO) * tanha(cst[ci + 1]);

                int j = (wn * 8 + ul) * 4 + t4;
                *(__half*)(hWr + rowA * ASTR + j * 2) = __float2half_rn(hA);
                *(__half*)(hWr + (rowA + 8) * ASTR + j * 2) = __float2half_rn(hB);
            }
        }
        __syncthreads();
    }

    // ---- fused MLP: final h in buffer A0 ----
    float* sW1 = (float*)(sm + SML_W1);
    for (int idx = tid; idx < 128 * 128; idx += 512) sW1[idx] = mlp_W1[idx];
    __syncthreads();

    int m = tid & 63, jb = (tid >> 6) * 16;
    u64 m1[8];
#pragma unroll
    for (int p = 0; p < 8; p++) m1[p] = pack2(mlp_b1[jb + 2 * p], mlp_b1[jb + 2 * p + 1]);
    const __half* hrow = (const __half*)(sm + SML_A0 + m * ASTR);
#pragma unroll 4
    for (int k = 0; k < 128; k++) {
        u64 hd = dup2(__half2float(hrow[k]));
        const u64* wp = (const u64*)&sW1[k * 128 + jb];
#pragma unroll
        for (int p = 0; p < 8; p++) m1[p] = ffma2(wp[p], hd, m1[p]);
    }
    float v = 0.0f;
#pragma unroll
    for (int p = 0; p < 8; p++) {
        float2 a = up2(m1[p]);
        v += fmaxf(a.x, 0.0f) * mlp_W2[jb + 2 * p]
           + fmaxf(a.y, 0.0f) * mlp_W2[jb + 2 * p + 1];
    }
    float* part = (float*)(sm + SML_PART);
    part[m * 8 + (tid >> 6)] = v;
    __syncthreads();
    if (tid < 64) {
        float s = mlp_b2[0];
#pragma unroll
        for (int p = 0; p < 8; p++) s += part[tid * 8 + p];
        scores_out[n0 + tid] = s;
    }
}

// ---------------- L4: logsumexp + BCE ----------------
__global__ void k_final(const float* __restrict__ label, float* __restrict__ out) {
    __shared__ float red[Bsz];
    int b = threadIdx.x;
    const float* sc = out + 1 + Bsz + b * Pn;
    float mx = -1e30f;
#pragma unroll
    for (int p = 0; p < Pn; p++) mx = fmaxf(mx, sc[p] * 0.5f);
    float s = 0.0f;
#pragma unroll
    for (int p = 0; p < Pn; p++) s += expf(sc[p] * 0.5f - mx);
    float lse = mx + logf(s);
    float pr = 1.0f / (1.0f + expf(-lse));
    out[1 + b] = pr;
    float pc = fminf(fmaxf(pr, 1e-7f), 1.0f - 1e-7f);
    float lb = label[b];
    red[b] = -(lb * logf(pc) + (1.0f - lb) * logf(1.0f - pc));
    __syncthreads();
    for (int st = Bsz / 2; st > 0; st >>= 1) {
        if (b < st) red[b] += red[b + st];
        __syncthreads();
    }
    if (b == 0) out[0] = red[0] / (float)Bsz;
}

// ---------------- launch ----------------
extern "C" void kernel_launch(void* const* d_in, const int* in_sizes, int n_in,
                              void* d_out, int out_size) {
    const int*   item1     = (const int*)d_in[0];
    const int*   item2     = (const int*)d_in[1];
    const int*   paths     = (const int*)d_in[2];
    const int*   edges     = (const int*)d_in[3];
    const float* label     = (const float*)d_in[4];
    const float* doc_table = (const float*)d_in[5];
    const float* ent_table = (const float*)d_in[6];
    const float* rel_table = (const float*)d_in[7];
    const float* nc_W1 = (const float*)d_in[8];
    const float* nc_b1 = (const float*)d_in[9];
    const float* nc_W2 = (const float*)d_in[10];
    const float* nc_b2 = (const float*)d_in[11];
    const float* ec_W  = (const float*)d_in[12];
    const float* ec_b  = (const float*)d_in[13];
    const float* rc_W  = (const float*)d_in[14];
    const float* rc_b  = (const float*)d_in[15];
    const float* W_ih  = (const float*)d_in[16];
    const float* W_hh  = (const float*)d_in[17];
    const float* b_ih  = (const float*)d_in[18];
    const float* b_hh  = (const float*)d_in[19];
    const float* mlp_W1 = (const float*)d_in[20];
    const float* mlp_b1 = (const float*)d_in[21];
    const float* mlp_W2 = (const float*)d_in[22];
    const float* mlp_b2 = (const float*)d_in[23];
    float* out = (float*)d_out;

    cudaFuncSetAttribute(k_compress_rel, cudaFuncAttributeMaxDynamicSharedMemorySize, SMC_TOTAL);
    cudaFuncSetAttribute(k_gemm_mma, cudaFuncAttributeMaxDynamicSharedMemorySize, SMG_TOTAL);
    cudaFuncSetAttribute(k_lstm_mma, cudaFuncAttributeMaxDynamicSharedMemorySize, SML_TOTAL);

    k_news_transpose<<<768, 128>>>(item1, item2, doc_table, nc_W1, nc_b1, nc_W2, nc_b2,
                                   W_ih, W_hh, ec_W);
    k_compress_rel<<<NPL / 128 + NREL, 512, SMC_TOTAL>>>(paths, ent_table, ec_b,
                                                         rel_table, rc_W, rc_b, b_ih, b_hh);
    k_gemm_mma<<<MTOT / 128, 512, SMG_TOTAL>>>();
    k_lstm_mma<<<Nseq / 64, 512, SML_TOTAL>>>(edges, mlp_W1, mlp_b1, mlp_W2, mlp_b2,
                                              out + 1 + Bsz);
    k_final<<<1, Bsz>>>(label, out);
}

// round 11
// speedup vs baseline: 1.2611x; 1.0046x over previous
#include <cuda_runtime.h>
#include <cuda_fp16.h>
#include <math.h>
#include <stdint.h>

typedef unsigned long long u64;

#define Bsz   1024
#define Pn    20
#define Ln    3
#define Tn    5
#define En    128
#define Nseq  (Bsz*Pn)          /* 20480 */
#define NPL   (Bsz*Pn*Ln)       /* 61440 */
#define NREL  60
#define DDOC  768
#define DENT  100
#define KPAD  112
#define MTOT  (NPL + 2*Bsz)     /* 63488 = 496*128 */

// ---------------- device scratch ----------------
__device__ __half g_AE [(size_t)MTOT * 128];
__device__ __half g_Bn [512 * 128];             // W_ih[:,0:128], rows in c' gate-pair order
__device__ __half g_Bh [512 * 128];             // W_hh, rows in c' gate-pair order
__device__ __half g_Wec[128 * KPAD];
__device__ float  g_WTrel[128 * 512];           // f32 [k][c']
__device__ float  g_relGb[NREL * 512];          // per-thread-contiguous gate layout
__device__ __half g_G16 [(size_t)MTOT * 512];   // per-thread-contiguous gate layout

// c' mapping: u=c'>>4, half=(c'>>3)&1, t=(c'>>1)&3, gb=c'&1 -> j=u*4+t, gate=half*2+gb
// storage pos(j,gate) = (j>>5)*128 + (j&3)*32 + ((j>>2)&7)*4 + gate

// ---- fast transcendentals ----
__device__ __forceinline__ float tanha(float x) {
    float y; asm("tanh.approx.f32 %0, %1;" : "=f"(y) : "f"(x)); return y;
}
__device__ __forceinline__ float siga(float x) {
    return fmaf(tanha(x * 0.5f), 0.5f, 0.5f);
}

// ---- f32x2 helpers ----
__device__ __forceinline__ u64 ffma2(u64 a, u64 b, u64 c) {
    u64 d; asm("fma.rn.f32x2 %0, %1, %2, %3;" : "=l"(d) : "l"(a), "l"(b), "l"(c)); return d;
}
__device__ __forceinline__ u64 dup2(float x) {
    u64 d; unsigned xi = __float_as_uint(x);
    asm("mov.b64 %0, {%1, %1};" : "=l"(d) : "r"(xi)); return d;
}
__device__ __forceinline__ u64 pack2(float lo, float hi) {
    u64 d; asm("mov.b64 %0, {%1, %2};" : "=l"(d) : "r"(__float_as_uint(lo)), "r"(__float_as_uint(hi)));
    return d;
}
__device__ __forceinline__ float2 up2(u64 v) {
    unsigned lo, hi; asm("mov.b64 {%0, %1}, %2;" : "=r"(lo), "=r"(hi) : "l"(v));
    return make_float2(__uint_as_float(lo), __uint_as_float(hi));
}

// ---- mma / ldmatrix ----
__device__ __forceinline__ uint32_t s2u(const void* p) {
    uint32_t a;
    asm("{ .reg .u64 t; cvta.to.shared.u64 t, %1; cvt.u32.u64 %0, t; }" : "=r"(a) : "l"(p));
    return a;
}
__device__ __forceinline__ void ldmA(uint32_t* r, uint32_t addr) {
    asm volatile("ldmatrix.sync.aligned.m8n8.x4.shared.b16 {%0,%1,%2,%3}, [%4];"
                 : "=r"(r[0]), "=r"(r[1]), "=r"(r[2]), "=r"(r[3]) : "r"(addr));
}
__device__ __forceinline__ void ldmB(uint32_t* r, uint32_t addr) {
    asm volatile("ldmatrix.sync.aligned.m8n8.x2.shared.b16 {%0,%1}, [%2];"
                 : "=r"(r[0]), "=r"(r[1]) : "r"(addr));
}
// x4 B load: 2 consecutive n-tile fragments (lanes 16-31 address the 2nd tile)
__device__ __forceinline__ void ldmB4(uint32_t* r, uint32_t addr) {
    asm volatile("ldmatrix.sync.aligned.m8n8.x4.shared.b16 {%0,%1,%2,%3}, [%4];"
                 : "=r"(r[0]), "=r"(r[1]), "=r"(r[2]), "=r"(r[3]) : "r"(addr));
}
__device__ __forceinline__ void mma16816(float* d, const uint32_t* a, const uint32_t* b) {
    asm volatile("mma.sync.aligned.m16n8k16.row.col.f32.f16.f16.f32 "
        "{%0,%1,%2,%3}, {%4,%5,%6,%7}, {%8,%9}, {%0,%1,%2,%3};"
        : "+f"(d[0]), "+f"(d[1]), "+f"(d[2]), "+f"(d[3])
        : "r"(a[0]), "r"(a[1]), "r"(a[2]), "r"(a[3]), "r"(b[0]), "r"(b[1]));
}

#define ASTR  272
#define CKSTR 240
#define DSTR  10

// ---------------- L0: news (blocks 0..255) + weight transpose (blocks 256..767) ----------
__global__ void k_news_transpose(const int* __restrict__ item1, const int* __restrict__ item2,
                                 const float* __restrict__ doc_table,
                                 const float* __restrict__ W1, const float* __restrict__ b1,
                                 const float* __restrict__ W2, const float* __restrict__ b2,
                                 const float* __restrict__ W_ih, const float* __restrict__ W_hh,
                                 const float* __restrict__ ec_W) {
    __shared__ __align__(16) float dsp[DDOC * DSTR];
    __shared__ __align__(16) float h1p[En * DSTR];
    __shared__ int items[8];
    int tid = threadIdx.x;

    if (blockIdx.x >= 256) {
        int idx = (blockIdx.x - 256) * 128 + tid;
        if (idx < 128 * KPAD) {
            int c = idx / KPAD, k = idx - c * KPAD;
            g_Wec[idx] = (k < DENT) ? __float2half_rn(ec_W[k * 128 + c]) : __half(0.0f);
        }
        int c = idx >> 7, k = idx & 127;
        int u = c >> 4, half = (c >> 3) & 1, t = (c >> 1) & 3, gb = c & 1;
        int j = u * 4 + t, gate = half * 2 + gb;
        int row = gate * 128 + j;
        g_Bn[c * 128 + k] = __float2half_rn(W_ih[row * 256 + k]);
        g_Bh[c * 128 + k] = __float2half_rn(W_hh[row * 128 + k]);
        g_WTrel[k * 512 + c] = W_ih[row * 256 + 128 + k];
        return;
    }

    int r0 = blockIdx.x * 8;
    if (tid < 8) {
        int row = r0 + tid;
        items[tid] = (row < Bsz) ? item1[row] : item2[row - Bsz];
    }
    __syncthreads();
    for (int k = tid; k < DDOC; k += 128) {
#pragma unroll
        for (int r = 0; r < 8; r++)
            dsp[k * DSTR + r] = doc_table[(size_t)items[r] * DDOC + k];
    }
    __syncthreads();
    u64 acc2[4];
    u64 bd = dup2(b1[tid]);
#pragma unroll
    for (int p = 0; p < 4; p++) acc2[p] = bd;
    for (int k = 0; k < DDOC; k++) {
        u64 wd = dup2(W1[k * En + tid]);
        const u64* hp = (const u64*)&dsp[k * DSTR];
#pragma unroll
        for (int p = 0; p < 4; p++) acc2[p] = ffma2(hp[p], wd, acc2[p]);
    }
#pragma unroll
    for (int p = 0; p < 4; p++) {
        float2 a = up2(acc2[p]);
        h1p[tid * DSTR + 2 * p]     = (a.x > 0.0f) ? a.x : expm1f(a.x);
        h1p[tid * DSTR + 2 * p + 1] = (a.y > 0.0f) ? a.y : expm1f(a.y);
    }
    __syncthreads();
    u64 bd2 = dup2(b2[tid]);
#pragma unroll
    for (int p = 0; p < 4; p++) acc2[p] = bd2;
    for (int k = 0; k < En; k++) {
        u64 wd = dup2(W2[k * En + tid]);
        const u64* hp = (const u64*)&h1p[k * DSTR];
#pragma unroll
        for (int p = 0; p < 4; p++) acc2[p] = ffma2(hp[p], wd, acc2[p]);
    }
#pragma unroll
    for (int p = 0; p < 4; p++) {
        float2 a = up2(acc2[p]);
        g_AE[(size_t)(NPL + r0 + 2 * p)     * En + tid] = __float2half_rn(tanhf(a.x));
        g_AE[(size_t)(NPL + r0 + 2 * p + 1) * En + tid] = __float2half_rn(tanhf(a.y));
    }
}

// ---------------- L1: entity compress (blocks 0..479) + relations (480..539) --------------
#define SMC_A 0
#define SMC_B (128 * CKSTR)
#define SMC_TOTAL (2 * 128 * CKSTR)
__global__ __launch_bounds__(512, 2) void k_compress_rel(const int* __restrict__ paths,
                                                         const float* __restrict__ ent_table,
                                                         const float* __restrict__ ec_b,
                                                         const float* __restrict__ rel_table,
                                                         const float* __restrict__ rc_W,
                                                         const float* __restrict__ rc_b,
                                                         const float* __restrict__ b_ih,
                                                         const float* __restrict__ b_hh) {
    extern __shared__ char sm[];
    __shared__ int spath[128];
    __shared__ float rr[DENT];
    __shared__ float rcs[En];
    int tid = threadIdx.x;

    if (blockIdx.x >= NPL / 128) {
        int rrow = blockIdx.x - NPL / 128;
        if (tid < DENT) rr[tid] = rel_table[rrow * DENT + tid];
        __syncthreads();
        if (tid < En) {
            float s = rc_b[tid];
            for (int k = 0; k < DENT; k++) s += rr[k] * rc_W[k * En + tid];
            rcs[tid] = tanhf(s);
        }
        __syncthreads();
        int c = tid;
        int u = c >> 4, half = (c >> 3) & 1, t = (c >> 1) & 3, gb = c & 1;
        int j = u * 4 + t, gate = half * 2 + gb;
        int gidx = gate * 128 + j;
        float s = b_ih[gidx] + b_hh[gidx];
        for (int k = 0; k < En; k++) s += rcs[k] * g_WTrel[k * 512 + c];
        int pos = (j >> 5) * 128 + (j & 3) * 32 + ((j >> 2) & 7) * 4 + gate;
        g_relGb[rrow * 512 + pos] = s;
        return;
    }

    int w = tid >> 5, l = tid & 31;
    int wm = w & 3, wn = w >> 2;
    int row0 = blockIdx.x * 128;

    if (tid < 128) spath[tid] = paths[row0 + tid];
    __syncthreads();
    for (int idx = tid; idx < 128 * 25; idx += 512) {
        int r = idx / 25, k4 = idx - r * 25;
        float4 v = *(const float4*)(ent_table + (size_t)spath[r] * DENT + k4 * 4);
        uint2 u2;
        *((__half2*)&u2.x) = __floats2half2_rn(v.x, v.y);
        *((__half2*)&u2.y) = __floats2half2_rn(v.z, v.w);
        *(uint2*)(sm + SMC_A + r * CKSTR + k4 * 8) = u2;
    }
    for (int idx = tid; idx < 128 * 3; idx += 512) {
        int r = idx / 3, j = idx - r * 3;
        *(uint2*)(sm + SMC_A + r * CKSTR + 200 + j * 8) = make_uint2(0u, 0u);
    }
    for (int idx = tid; idx < 128 * 28; idx += 512) {
        int r = idx / 28, j = idx - r * 28;
        *(uint2*)(sm + SMC_B + r * CKSTR + j * 8) = ((const uint2*)g_Wec)[idx];
    }
    __syncthreads();

    uint32_t base = s2u(sm);
    int g8 = l & 7;
    uint32_t aBase = base + SMC_A + (uint32_t)(wm * 32 + g8 + ((l >> 3) & 1) * 8) * CKSTR
                   + ((l >> 4) & 1) * 16;
    uint32_t bBase = base + SMC_B + (uint32_t)(wn * 32 + g8) * CKSTR + ((l >> 3) & 1) * 16;

    float acc[2][4][4];
#pragma unroll
    for (int mt = 0; mt < 2; mt++)
#pragma unroll
        for (int nt = 0; nt < 4; nt++)
#pragma unroll
            for (int q = 0; q < 4; q++) acc[mt][nt][q] = 0.0f;

#pragma unroll
    for (int kt = 0; kt < 7; kt++) {
        uint32_t a[2][4];
        ldmA(a[0], aBase + kt * 32);
        ldmA(a[1], aBase + 16 * CKSTR + kt * 32);
#pragma unroll
        for (int nt = 0; nt < 4; nt++) {
            uint32_t b[2];
            ldmB(b, bBase + nt * 8 * CKSTR + kt * 32);
            mma16816(acc[0][nt], a[0], b);
            mma16816(acc[1][nt], a[1], b);
        }
    }
    __syncthreads();

    int tg = l & 3, gg = l >> 2;
#pragma unroll
    for (int mt = 0; mt < 2; mt++) {
        int r = wm * 32 + mt * 16 + gg;
#pragma unroll
        for (int nt = 0; nt < 4; nt++) {
            int cc = wn * 32 + nt * 8 + 2 * tg;
            float b0 = __ldg(ec_b + cc), b1 = __ldg(ec_b + cc + 1);
            *(__half2*)(sm + r * ASTR + cc * 2) =
                __floats2half2_rn(tanha(acc[mt][nt][0] + b0), tanha(acc[mt][nt][1] + b1));
            *(__half2*)(sm + (r + 8) * ASTR + cc * 2) =
                __floats2half2_rn(tanha(acc[mt][nt][2] + b0), tanha(acc[mt][nt][3] + b1));
        }
    }
    __syncthreads();
    for (int it = tid; it < 128 * 16; it += 512) {
        int r = it >> 4, bb = it & 15;
        uint4 v = *(uint4*)(sm + r * ASTR + bb * 16);
        *(uint4*)((char*)g_AE + (size_t)(row0 + r) * 256 + bb * 16) = v;
    }
}

// ---------------- L2: HMMA gate GEMM, A staged once, 4 N-chunks, 2 CTA/SM ----------------
#define SMG_A 0
#define SMG_B (128 * ASTR)
#define SMG_TOTAL (2 * 128 * ASTR)        /* 69632 */
__global__ __launch_bounds__(512, 2) void k_gemm_mma() {
    extern __shared__ char sm[];
    int tid = threadIdx.x, w = tid >> 5, l = tid & 31;
    int wm = w & 3, wn = w >> 2;
    int row0 = blockIdx.x * 128;

    const uint4* Ag = (const uint4*)g_AE;
    for (int idx = tid; idx < 128 * 16; idx += 512) {
        int r = idx >> 4, c4 = idx & 15;
        *(uint4*)(sm + SMG_A + r * ASTR + c4 * 16) = Ag[(size_t)(row0 + r) * 16 + c4];
    }

    uint32_t base = s2u(sm);
    int g8 = l & 7, tg = l & 3, gg = l >> 2;
    uint32_t aBase = base + SMG_A + (uint32_t)(wm * 32 + g8 + ((l >> 3) & 1) * 8) * ASTR
                   + ((l >> 4) & 1) * 16;
    uint32_t bBase = base + SMG_B + (uint32_t)(wn * 32 + g8) * ASTR + ((l >> 3) & 1) * 16;
    const uint4* Bg = (const uint4*)g_Bn;

    for (int nc = 0; nc < 4; nc++) {
        __syncthreads();
        for (int idx = tid; idx < 128 * 16; idx += 512) {
            int n = idx >> 4, c4 = idx & 15;
            *(uint4*)(sm + SMG_B + n * ASTR + c4 * 16) = Bg[(size_t)(nc * 128 + n) * 16 + c4];
        }
        __syncthreads();

        float acc[2][4][4];
#pragma unroll
        for (int mt = 0; mt < 2; mt++)
#pragma unroll
            for (int nt = 0; nt < 4; nt++)
#pragma unroll
                for (int q = 0; q < 4; q++) acc[mt][nt][q] = 0.0f;

#pragma unroll
        for (int kt = 0; kt < 8; kt++) {
            uint32_t a[2][4];
            ldmA(a[0], aBase + kt * 32);
            ldmA(a[1], aBase + 16 * ASTR + kt * 32);
#pragma unroll
            for (int nt = 0; nt < 4; nt++) {
                uint32_t b[2];
                ldmB(b, bBase + nt * 8 * ASTR + kt * 32);
                mma16816(acc[0][nt], a[0], b);
                mma16816(acc[1][nt], a[1], b);
            }
        }
        __syncthreads();   // B reads done; overlay C staging

#pragma unroll
        for (int mt = 0; mt < 2; mt++) {
            int r = wm * 32 + mt * 16 + gg;
#pragma unroll
            for (int nt = 0; nt < 4; nt++) {
                int pos2b = tg * 64 + (wn * 2 + (nt >> 1)) * 8 + (nt & 1) * 4;
                *(__half2*)(sm + SMG_B + r * ASTR + pos2b) =
                    __floats2half2_rn(acc[mt][nt][0], acc[mt][nt][1]);
                *(__half2*)(sm + SMG_B + (r + 8) * ASTR + pos2b) =
                    __floats2half2_rn(acc[mt][nt][2], acc[mt][nt][3]);
            }
        }
        __syncthreads();
        for (int it = tid; it < 128 * 16; it += 512) {
            int r = it >> 4, bb = it & 15;
            uint4 v = *(uint4*)(sm + SMG_B + r * ASTR + bb * 16);
            *(uint4*)((char*)g_G16 + (size_t)(row0 + r) * 1024 + nc * 256 + bb * 16) = v;
        }
    }
}

// ---------------- L3: HMMA LSTM + fused MLP (256 threads, 256-reg budget, no spills) -----
#define SML_A0 0
#define SML_A1 (64 * ASTR)
#define SML_B  (2 * 64 * ASTR)
#define SML_W1 SML_B
#define SML_PART (SML_B + 512 * ASTR)
#define SML_TOTAL (SML_PART + 2048)
__global__ __launch_bounds__(256, 1) void k_lstm_mma(const int* __restrict__ edges,
                                                     const float* __restrict__ mlp_W1,
                                                     const float* __restrict__ mlp_b1,
                                                     const float* __restrict__ mlp_W2,
                                                     const float* __restrict__ mlp_b2,
                                                     float* __restrict__ scores_out) {
    extern __shared__ char sm[];
    int tid = threadIdx.x, w = tid >> 5, l = tid & 31;
    int wm = w & 3, wn = w >> 2;          // wn in {0,1}: 256 c'-cols per warp
    int n0 = blockIdx.x * 64;
    int g8 = l & 7, t4 = l & 3, gg = l >> 2;

    const uint4* Bg = (const uint4*)g_Bh;
    for (int idx = tid; idx < 512 * 16; idx += 256) {
        int n = idx >> 4, c4 = idx & 15;
        *(uint4*)(sm + SML_B + n * ASTR + c4 * 16) = Bg[(size_t)n * 16 + c4];
    }
    __syncthreads();

    uint32_t base = s2u(sm);
    uint32_t aLane = (uint32_t)(wm * 16 + g8 + ((l >> 3) & 1) * 8) * ASTR + ((l >> 4) & 1) * 16;
    // x4 B address: lanes 0-15 -> n-tile ni, lanes 16-31 -> n-tile ni+1
    uint32_t bLane = base + SML_B + ((uint32_t)g8 + ((l >> 4) & 1) * 8) * ASTR
                   + ((l >> 3) & 1) * 16;

    int rowA = wm * 16 + gg;
    int seqA = n0 + rowA, seqB = seqA + 8;
    int bA = seqA / Pn, bB = seqB / Pn;

    float cst[32];
#pragma unroll
    for (int q = 0; q < 32; q++) cst[q] = 0.0f;

    for (int t = 0; t < Tn; t++) {
        uint32_t aRd = base + ((t & 1) ? SML_A0 : SML_A1) + aLane;
        char* hWr = sm + ((t & 1) ? SML_A1 : SML_A0);
        int rowGA = (t == 0) ? NPL + bA : (t == 4) ? NPL + Bsz + bA : seqA * Ln + (t - 1);
        int rowGB = (t == 0) ? NPL + bB : (t == 4) ? NPL + Bsz + bB : seqB * Ln + (t - 1);
        int eA = (t < Ln) ? edges[seqA * Ln + t] : 0;
        int eB = (t < Ln) ? edges[seqB * Ln + t] : 0;
        const char* gAr = (const char*)g_G16 + (size_t)rowGA * 1024;
        const char* gBr = (const char*)g_G16 + (size_t)rowGB * 1024;
        const float* rAr = g_relGb + (size_t)eA * 512;
        const float* rBr = g_relGb + (size_t)eB * 512;

        // hoist A fragments for the whole step (32 regs)
        uint32_t afr[8][4];
        if (t > 0) {
#pragma unroll
            for (int kt = 0; kt < 8; kt++) ldmA(afr[kt], aRd + kt * 32);
        }

#pragma unroll
        for (int qh = 0; qh < 2; qh++) {
            int quad = wn * 2 + qh;
            const char* gA = gAr + quad * 256 + t4 * 64;
            const char* gB = gBr + quad * 256 + t4 * 64;
            const float* rA = rAr + quad * 128 + t4 * 32;
            const float* rB = rBr + quad * 128 + t4 * 32;
            uint32_t bQuad = bLane + (uint32_t)(quad * 128) * ASTR;

#pragma unroll
            for (int qc = 0; qc < 4; qc++) {
                uint4 guA = *(const uint4*)(gA + qc * 16);
                uint4 guB = *(const uint4*)(gB + qc * 16);
                float4 rA0 = *(const float4*)(rA + qc * 8);
                float4 rA1 = *(const float4*)(rA + qc * 8 + 4);
                float4 rB0 = *(const float4*)(rB + qc * 8);
                float4 rB1 = *(const float4*)(rB + qc * 8 + 4);

                float acc[4][4];
#pragma unroll
                for (int ni = 0; ni < 4; ni++)
#pragma unroll
                    for (int q = 0; q < 4; q++) acc[ni][q] = 0.0f;
                if (t > 0) {
#pragma unroll
                    for (int kt = 0; kt < 8; kt++) {
#pragma unroll
                        for (int np = 0; np < 2; np++) {   // pairs of n-tiles via x4
                            uint32_t b4[4];
                            ldmB4(b4, bQuad + (qc * 4 + np * 2) * 8 * ASTR + kt * 32);
                            mma16816(acc[np * 2],     afr[kt], b4);
                            mma16816(acc[np * 2 + 1], afr[kt], b4 + 2);
                        }
                    }
                }
#pragma unroll
                for (int p = 0; p < 2; p++) {
                    int ul = qc * 2 + p;
                    float2 fifA = __half22float2(((const __half2*)&guA)[p * 2 + 0]);
                    float2 fgoA = __half22float2(((const __half2*)&guA)[p * 2 + 1]);
                    float2 fifB = __half22float2(((const __half2*)&guB)[p * 2 + 0]);
                    float2 fgoB = __half22float2(((const __half2*)&guB)[p * 2 + 1]);
                    float4 ra = p ? rA1 : rA0;
                    float4 rb = p ? rB1 : rB0;
                    float gi = acc[2 * p][0] + fifA.x + ra.x;
                    float gf = acc[2 * p][1] + fifA.y + ra.y;
                    float gG = acc[2 * p + 1][0] + fgoA.x + ra.z;
                    float gO = acc[2 * p + 1][1] + fgoA.y + ra.w;
                    int ci = qh * 16 + ul * 2;
                    cst[ci] = siga(gf) * cst[ci] + siga(gi) * tanha(gG);
                    float hA = siga(gO) * tanha(cst[ci]);
                    gi = acc[2 * p][2] + fifB.x + rb.x;
                    gf = acc[2 * p][3] + fifB.y + rb.y;
                    gG = acc[2 * p + 1][2] + fgoB.x + rb.z;
                    gO = acc[2 * p + 1][3] + fgoB.y + rb.w;
                    cst[ci + 1] = siga(gf) * cst[ci + 1] + siga(gi) * tanha(gG);
                    float hB = siga(gO) * tanha(cst[ci + 1]);

                    int j = (quad * 8 + ul) * 4 + t4;
                    *(__half*)(hWr + rowA * ASTR + j * 2) = __float2half_rn(hA);
                    *(__half*)(hWr + (rowA + 8) * ASTR + j * 2) = __float2half_rn(hB);
                }
            }
        }
        __syncthreads();
    }

    // ---- fused MLP: final h in buffer A0 (256 threads: 4 groups x 32 j) ----
    float* sW1 = (float*)(sm + SML_W1);
    for (int idx = tid; idx < 128 * 128; idx += 256) sW1[idx] = mlp_W1[idx];
    __syncthreads();

    int m = tid & 63, grp = tid >> 6, jb = grp * 32;
    u64 m1[16];
#pragma unroll
    for (int p = 0; p < 16; p++) m1[p] = pack2(mlp_b1[jb + 2 * p], mlp_b1[jb + 2 * p + 1]);
    const __half* hrow = (const __half*)(sm + SML_A0 + m * ASTR);
#pragma unroll 4
    for (int k = 0; k < 128; k++) {
        u64 hd = dup2(__half2float(hrow[k]));
        const u64* wp = (const u64*)&sW1[k * 128 + jb];
#pragma unroll
        for (int p = 0; p < 16; p++) m1[p] = ffma2(wp[p], hd, m1[p]);
    }
    float v = 0.0f;
#pragma unroll
    for (int p = 0; p < 16; p++) {
        float2 a = up2(m1[p]);
        v += fmaxf(a.x, 0.0f) * mlp_W2[jb + 2 * p]
           + fmaxf(a.y, 0.0f) * mlp_W2[jb + 2 * p + 1];
    }
    float* part = (float*)(sm + SML_PART);
    part[m * 4 + grp] = v;
    __syncthreads();
    if (tid < 64) {
        float s = mlp_b2[0] + part[tid * 4] + part[tid * 4 + 1]
                + part[tid * 4 + 2] + part[tid * 4 + 3];
        scores_out[n0 + tid] = s;
    }
}

// ---------------- L4: logsumexp + BCE ----------------
__global__ void k_final(const float* __restrict__ label, float* __restrict__ out) {
    __shared__ float red[Bsz];
    int b = threadIdx.x;
    const float* sc = out + 1 + Bsz + b * Pn;
    float mx = -1e30f;
#pragma unroll
    for (int p = 0; p < Pn; p++) mx = fmaxf(mx, sc[p] * 0.5f);
    float s = 0.0f;
#pragma unroll
    for (int p = 0; p < Pn; p++) s += expf(sc[p] * 0.5f - mx);
    float lse = mx + logf(s);
    float pr = 1.0f / (1.0f + expf(-lse));
    out[1 + b] = pr;
    float pc = fminf(fmaxf(pr, 1e-7f), 1.0f - 1e-7f);
    float lb = label[b];
    red[b] = -(lb * logf(pc) + (1.0f - lb) * logf(1.0f - pc));
    __syncthreads();
    for (int st = Bsz / 2; st > 0; st >>= 1) {
        if (b < st) red[b] += red[b + st];
        __syncthreads();
    }
    if (b == 0) out[0] = red[0] / (float)Bsz;
}

// ---------------- launch ----------------
extern "C" void kernel_launch(void* const* d_in, const int* in_sizes, int n_in,
                              void* d_out, int out_size) {
    const int*   item1     = (const int*)d_in[0];
    const int*   item2     = (const int*)d_in[1];
    const int*   paths     = (const int*)d_in[2];
    const int*   edges     = (const int*)d_in[3];
    const float* label     = (const float*)d_in[4];
    const float* doc_table = (const float*)d_in[5];
    const float* ent_table = (const float*)d_in[6];
    const float* rel_table = (const float*)d_in[7];
    const float* nc_W1 = (const float*)d_in[8];
    const float* nc_b1 = (const float*)d_in[9];
    const float* nc_W2 = (const float*)d_in[10];
    const float* nc_b2 = (const float*)d_in[11];
    const float* ec_W  = (const float*)d_in[12];
    const float* ec_b  = (const float*)d_in[13];
    const float* rc_W  = (const float*)d_in[14];
    const float* rc_b  = (const float*)d_in[15];
    const float* W_ih  = (const float*)d_in[16];
    const float* W_hh  = (const float*)d_in[17];
    const float* b_ih  = (const float*)d_in[18];
    const float* b_hh  = (const float*)d_in[19];
    const float* mlp_W1 = (const float*)d_in[20];
    const float* mlp_b1 = (const float*)d_in[21];
    const float* mlp_W2 = (const float*)d_in[22];
    const float* mlp_b2 = (const float*)d_in[23];
    float* out = (float*)d_out;

    cudaFuncSetAttribute(k_compress_rel, cudaFuncAttributeMaxDynamicSharedMemorySize, SMC_TOTAL);
    cudaFuncSetAttribute(k_gemm_mma, cudaFuncAttributeMaxDynamicSharedMemorySize, SMG_TOTAL);
    cudaFuncSetAttribute(k_lstm_mma, cudaFuncAttributeMaxDynamicSharedMemorySize, SML_TOTAL);

    k_news_transpose<<<768, 128>>>(item1, item2, doc_table, nc_W1, nc_b1, nc_W2, nc_b2,
                                   W_ih, W_hh, ec_W);
    k_compress_rel<<<NPL / 128 + NREL, 512, SMC_TOTAL>>>(paths, ent_table, ec_b,
                                                         rel_table, rc_W, rc_b, b_ih, b_hh);
    k_gemm_mma<<<MTOT / 128, 512, SMG_TOTAL>>>();
    k_lstm_mma<<<Nseq / 64, 256, SML_TOTAL>>>(edges, mlp_W1, mlp_b1, mlp_W2, mlp_b2,
                                              out + 1 + Bsz);
    k_final<<<1, Bsz>>>(label, out);
}

// round 12
// speedup vs baseline: 1.3705x; 1.0868x over previous
#include <cuda_runtime.h>
#include <cuda_fp16.h>
#include <math.h>
#include <stdint.h>

typedef unsigned long long u64;

#define Bsz   1024
#define Pn    20
#define Ln    3
#define Tn    5
#define En    128
#define Nseq  (Bsz*Pn)          /* 20480 */
#define NPL   (Bsz*Pn*Ln)       /* 61440 */
#define NREL  60
#define DDOC  768
#define DENT  100
#define KPAD  112
#define MTOT  (NPL + 2*Bsz)     /* 63488 = 496*128 */

// ---------------- device scratch ----------------
__device__ __half g_AE [(size_t)MTOT * 128];
__device__ __half g_Bn [512 * 128];             // W_ih[:,0:128], PLAIN rows c'=gate*128+j
__device__ __half g_Bh [512 * 128];             // W_hh, PLAIN rows
__device__ __half g_W1h[128 * 128];             // mlp_W1^T f16: [n][k]
__device__ __half g_Wec[128 * KPAD];
__device__ float  g_WTrel[128 * 512];           // f32 [k][c'] plain
__device__ __half g_relGb16[NREL * 512];        // [e][64 jp][i0,i1,f0,f1,g0,g1,o0,o1]
__device__ __half g_G16 [(size_t)MTOT * 512];   // [row][64 jp][8 gate-halves]

// ---- fast transcendentals ----
__device__ __forceinline__ float tanha(float x) {
    float y; asm("tanh.approx.f32 %0, %1;" : "=f"(y) : "f"(x)); return y;
}
__device__ __forceinline__ float siga(float x) {
    return fmaf(tanha(x * 0.5f), 0.5f, 0.5f);
}

// ---- f32x2 helpers ----
__device__ __forceinline__ u64 ffma2(u64 a, u64 b, u64 c) {
    u64 d; asm("fma.rn.f32x2 %0, %1, %2, %3;" : "=l"(d) : "l"(a), "l"(b), "l"(c)); return d;
}
__device__ __forceinline__ u64 dup2(float x) {
    u64 d; unsigned xi = __float_as_uint(x);
    asm("mov.b64 %0, {%1, %1};" : "=l"(d) : "r"(xi)); return d;
}
__device__ __forceinline__ float2 up2(u64 v) {
    unsigned lo, hi; asm("mov.b64 {%0, %1}, %2;" : "=r"(lo), "=r"(hi) : "l"(v));
    return make_float2(__uint_as_float(lo), __uint_as_float(hi));
}

// ---- mma / ldmatrix ----
__device__ __forceinline__ uint32_t s2u(const void* p) {
    uint32_t a;
    asm("{ .reg .u64 t; cvta.to.shared.u64 t, %1; cvt.u32.u64 %0, t; }" : "=r"(a) : "l"(p));
    return a;
}
__device__ __forceinline__ void ldmA(uint32_t* r, uint32_t addr) {
    asm volatile("ldmatrix.sync.aligned.m8n8.x4.shared.b16 {%0,%1,%2,%3}, [%4];"
                 : "=r"(r[0]), "=r"(r[1]), "=r"(r[2]), "=r"(r[3]) : "r"(addr));
}
__device__ __forceinline__ void ldmB(uint32_t* r, uint32_t addr) {
    asm volatile("ldmatrix.sync.aligned.m8n8.x2.shared.b16 {%0,%1}, [%2];"
                 : "=r"(r[0]), "=r"(r[1]) : "r"(addr));
}
__device__ __forceinline__ void ldmB4(uint32_t* r, uint32_t addr) {
    asm volatile("ldmatrix.sync.aligned.m8n8.x4.shared.b16 {%0,%1,%2,%3}, [%4];"
                 : "=r"(r[0]), "=r"(r[1]), "=r"(r[2]), "=r"(r[3]) : "r"(addr));
}
__device__ __forceinline__ void mma16816(float* d, const uint32_t* a, const uint32_t* b) {
    asm volatile("mma.sync.aligned.m16n8k16.row.col.f32.f16.f16.f32 "
        "{%0,%1,%2,%3}, {%4,%5,%6,%7}, {%8,%9}, {%0,%1,%2,%3};"
        : "+f"(d[0]), "+f"(d[1]), "+f"(d[2]), "+f"(d[3])
        : "r"(a[0]), "r"(a[1]), "r"(a[2]), "r"(a[3]), "r"(b[0]), "r"(b[1]));
}

#define ASTR  272
#define CKSTR 240
#define DSTR  10
#define CSTR2 1040   /* gemm full-row C staging stride */

// ---------------- L0: news (blocks 0..255) + weight pack (blocks 256..767) ---------------
__global__ void k_news_transpose(const int* __restrict__ item1, const int* __restrict__ item2,
                                 const float* __restrict__ doc_table,
                                 const float* __restrict__ W1, const float* __restrict__ b1,
                                 const float* __restrict__ W2, const float* __restrict__ b2,
                                 const float* __restrict__ W_ih, const float* __restrict__ W_hh,
                                 const float* __restrict__ ec_W, const float* __restrict__ mlp_W1) {
    __shared__ __align__(16) float dsp[DDOC * DSTR];
    __shared__ __align__(16) float h1p[En * DSTR];
    __shared__ int items[8];
    int tid = threadIdx.x;

    if (blockIdx.x >= 256) {
        int idx = (blockIdx.x - 256) * 128 + tid;
        if (idx < 128 * KPAD) {
            int c = idx / KPAD, k = idx - c * KPAD;
            g_Wec[idx] = (k < DENT) ? __float2half_rn(ec_W[k * 128 + c]) : __half(0.0f);
        }
        if (idx < 128 * 128) {
            int n = idx >> 7, k = idx & 127;
            g_W1h[idx] = __float2half_rn(mlp_W1[k * 128 + n]);
        }
        int c = idx >> 7, k = idx & 127;   // plain row c = torch row
        g_Bn[idx] = __float2half_rn(W_ih[c * 256 + k]);
        g_Bh[idx] = __float2half_rn(W_hh[c * 128 + k]);
        g_WTrel[k * 512 + c] = W_ih[c * 256 + 128 + k];
        return;
    }

    int r0 = blockIdx.x * 8;
    if (tid < 8) {
        int row = r0 + tid;
        items[tid] = (row < Bsz) ? item1[row] : item2[row - Bsz];
    }
    __syncthreads();
    for (int k = tid; k < DDOC; k += 128) {
#pragma unroll
        for (int r = 0; r < 8; r++)
            dsp[k * DSTR + r] = doc_table[(size_t)items[r] * DDOC + k];
    }
    __syncthreads();
    u64 acc2[4];
    u64 bd = dup2(b1[tid]);
#pragma unroll
    for (int p = 0; p < 4; p++) acc2[p] = bd;
    for (int k = 0; k < DDOC; k++) {
        u64 wd = dup2(W1[k * En + tid]);
        const u64* hp = (const u64*)&dsp[k * DSTR];
#pragma unroll
        for (int p = 0; p < 4; p++) acc2[p] = ffma2(hp[p], wd, acc2[p]);
    }
#pragma unroll
    for (int p = 0; p < 4; p++) {
        float2 a = up2(acc2[p]);
        h1p[tid * DSTR + 2 * p]     = (a.x > 0.0f) ? a.x : expm1f(a.x);
        h1p[tid * DSTR + 2 * p + 1] = (a.y > 0.0f) ? a.y : expm1f(a.y);
    }
    __syncthreads();
    u64 bd2 = dup2(b2[tid]);
#pragma unroll
    for (int p = 0; p < 4; p++) acc2[p] = bd2;
    for (int k = 0; k < En; k++) {
        u64 wd = dup2(W2[k * En + tid]);
        const u64* hp = (const u64*)&h1p[k * DSTR];
#pragma unroll
        for (int p = 0; p < 4; p++) acc2[p] = ffma2(hp[p], wd, acc2[p]);
    }
#pragma unroll
    for (int p = 0; p < 4; p++) {
        float2 a = up2(acc2[p]);
        g_AE[(size_t)(NPL + r0 + 2 * p)     * En + tid] = __float2half_rn(tanhf(a.x));
        g_AE[(size_t)(NPL + r0 + 2 * p + 1) * En + tid] = __float2half_rn(tanhf(a.y));
    }
}

// ---------------- L1: entity compress (blocks 0..479) + relations (480..539) --------------
#define SMC_A 0
#define SMC_B (128 * CKSTR)
#define SMC_TOTAL (2 * 128 * CKSTR)
__global__ __launch_bounds__(512, 2) void k_compress_rel(const int* __restrict__ paths,
                                                         const float* __restrict__ ent_table,
                                                         const float* __restrict__ ec_b,
                                                         const float* __restrict__ rel_table,
                                                         const float* __restrict__ rc_W,
                                                         const float* __restrict__ rc_b,
                                                         const float* __restrict__ b_ih,
                                                         const float* __restrict__ b_hh) {
    extern __shared__ char sm[];
    __shared__ int spath[128];
    __shared__ float rr[DENT];
    __shared__ float rcs[En];
    int tid = threadIdx.x;

    if (blockIdx.x >= NPL / 128) {
        int rrow = blockIdx.x - NPL / 128;
        if (tid < DENT) rr[tid] = rel_table[rrow * DENT + tid];
        __syncthreads();
        if (tid < En) {
            float s = rc_b[tid];
            for (int k = 0; k < DENT; k++) s += rr[k] * rc_W[k * En + tid];
            rcs[tid] = tanhf(s);
        }
        __syncthreads();
        int c = tid;                       // plain: gate = c>>7, j = c&127
        int gate = c >> 7, j = c & 127;
        float s = b_ih[c] + b_hh[c];
        for (int k = 0; k < En; k++) s += rcs[k] * g_WTrel[k * 512 + c];
        g_relGb16[rrow * 512 + (j >> 1) * 8 + gate * 2 + (j & 1)] = __float2half_rn(s);
        return;
    }

    int w = tid >> 5, l = tid & 31;
    int wm = w & 3, wn = w >> 2;
    int row0 = blockIdx.x * 128;

    if (tid < 128) spath[tid] = paths[row0 + tid];
    __syncthreads();
    for (int idx = tid; idx < 128 * 25; idx += 512) {
        int r = idx / 25, k4 = idx - r * 25;
        float4 v = *(const float4*)(ent_table + (size_t)spath[r] * DENT + k4 * 4);
        uint2 u2;
        *((__half2*)&u2.x) = __floats2half2_rn(v.x, v.y);
        *((__half2*)&u2.y) = __floats2half2_rn(v.z, v.w);
        *(uint2*)(sm + SMC_A + r * CKSTR + k4 * 8) = u2;
    }
    for (int idx = tid; idx < 128 * 3; idx += 512) {
        int r = idx / 3, j = idx - r * 3;
        *(uint2*)(sm + SMC_A + r * CKSTR + 200 + j * 8) = make_uint2(0u, 0u);
    }
    for (int idx = tid; idx < 128 * 28; idx += 512) {
        int r = idx / 28, j = idx - r * 28;
        *(uint2*)(sm + SMC_B + r * CKSTR + j * 8) = ((const uint2*)g_Wec)[idx];
    }
    __syncthreads();

    uint32_t base = s2u(sm);
    int g8 = l & 7;
    uint32_t aBase = base + SMC_A + (uint32_t)(wm * 32 + g8 + ((l >> 3) & 1) * 8) * CKSTR
                   + ((l >> 4) & 1) * 16;
    uint32_t bBase = base + SMC_B + (uint32_t)(wn * 32 + g8) * CKSTR + ((l >> 3) & 1) * 16;

    float acc[2][4][4];
#pragma unroll
    for (int mt = 0; mt < 2; mt++)
#pragma unroll
        for (int nt = 0; nt < 4; nt++)
#pragma unroll
            for (int q = 0; q < 4; q++) acc[mt][nt][q] = 0.0f;

#pragma unroll
    for (int kt = 0; kt < 7; kt++) {
        uint32_t a[2][4];
        ldmA(a[0], aBase + kt * 32);
        ldmA(a[1], aBase + 16 * CKSTR + kt * 32);
#pragma unroll
        for (int nt = 0; nt < 4; nt++) {
            uint32_t b[2];
            ldmB(b, bBase + nt * 8 * CKSTR + kt * 32);
            mma16816(acc[0][nt], a[0], b);
            mma16816(acc[1][nt], a[1], b);
        }
    }
    __syncthreads();

    int tg = l & 3, gg = l >> 2;
#pragma unroll
    for (int mt = 0; mt < 2; mt++) {
        int r = wm * 32 + mt * 16 + gg;
#pragma unroll
        for (int nt = 0; nt < 4; nt++) {
            int cc = wn * 32 + nt * 8 + 2 * tg;
            float b0 = __ldg(ec_b + cc), b1 = __ldg(ec_b + cc + 1);
            *(__half2*)(sm + r * ASTR + cc * 2) =
                __floats2half2_rn(tanha(acc[mt][nt][0] + b0), tanha(acc[mt][nt][1] + b1));
            *(__half2*)(sm + (r + 8) * ASTR + cc * 2) =
                __floats2half2_rn(tanha(acc[mt][nt][2] + b0), tanha(acc[mt][nt][3] + b1));
        }
    }
    __syncthreads();
    for (int it = tid; it < 128 * 16; it += 512) {
        int r = it >> 4, bb = it & 15;
        uint4 v = *(uint4*)(sm + r * ASTR + bb * 16);
        *(uint4*)((char*)g_AE + (size_t)(row0 + r) * 256 + bb * 16) = v;
    }
}

// ---------------- L2: HMMA gate GEMM -> interleaved jp-records, full-row staging ----------
#define SMG_A 0
#define SMG_B (128 * ASTR)                        /* 34816 */
#define SMG_C (2 * 128 * ASTR)                    /* 69632 */
#define SMG_TOTAL (SMG_C + 128 * CSTR2)           /* 202752 */
__global__ __launch_bounds__(512, 1) void k_gemm_mma() {
    extern __shared__ char sm[];
    int tid = threadIdx.x, w = tid >> 5, l = tid & 31;
    int wm = w & 3, wn = w >> 2;
    int row0 = blockIdx.x * 128;

    const uint4* Ag = (const uint4*)g_AE;
    for (int idx = tid; idx < 128 * 16; idx += 512) {
        int r = idx >> 4, c4 = idx & 15;
        *(uint4*)(sm + SMG_A + r * ASTR + c4 * 16) = Ag[(size_t)(row0 + r) * 16 + c4];
    }

    uint32_t base = s2u(sm);
    int g8 = l & 7, tg = l & 3, gg = l >> 2;
    uint32_t aBase = base + SMG_A + (uint32_t)(wm * 32 + g8 + ((l >> 3) & 1) * 8) * ASTR
                   + ((l >> 4) & 1) * 16;
    uint32_t bBase = base + SMG_B + (uint32_t)(wn * 32 + g8) * ASTR + ((l >> 3) & 1) * 16;
    const uint4* Bg = (const uint4*)g_Bn;

    for (int nc = 0; nc < 4; nc++) {               // nc = gate
        __syncthreads();
        for (int idx = tid; idx < 128 * 16; idx += 512) {
            int n = idx >> 4, c4 = idx & 15;
            *(uint4*)(sm + SMG_B + n * ASTR + c4 * 16) = Bg[(size_t)(nc * 128 + n) * 16 + c4];
        }
        __syncthreads();

        float acc[2][4][4];
#pragma unroll
        for (int mt = 0; mt < 2; mt++)
#pragma unroll
            for (int nt = 0; nt < 4; nt++)
#pragma unroll
                for (int q = 0; q < 4; q++) acc[mt][nt][q] = 0.0f;

#pragma unroll
        for (int kt = 0; kt < 8; kt++) {
            uint32_t a[2][4];
            ldmA(a[0], aBase + kt * 32);
            ldmA(a[1], aBase + 16 * ASTR + kt * 32);
#pragma unroll
            for (int nt = 0; nt < 4; nt++) {
                uint32_t b[2];
                ldmB(b, bBase + nt * 8 * ASTR + kt * 32);
                mma16816(acc[0][nt], a[0], b);
                mma16816(acc[1][nt], a[1], b);
            }
        }
        __syncthreads();   // ldmB done before next chunk's B overwrite

        // write into full-row staging: jp = tile*4 + tg, slot = nc
#pragma unroll
        for (int mt = 0; mt < 2; mt++) {
            int r = wm * 32 + mt * 16 + gg;
#pragma unroll
            for (int nt = 0; nt < 4; nt++) {
                int jp = (wn * 4 + nt) * 4 + tg;
                *(__half2*)(sm + SMG_C + r * CSTR2 + jp * 16 + nc * 4) =
                    __floats2half2_rn(acc[mt][nt][0], acc[mt][nt][1]);
                *(__half2*)(sm + SMG_C + (r + 8) * CSTR2 + jp * 16 + nc * 4) =
                    __floats2half2_rn(acc[mt][nt][2], acc[mt][nt][3]);
            }
        }
    }
    __syncthreads();
    for (int it = tid; it < 128 * 64; it += 512) {
        int r = it >> 6, q = it & 63;
        uint4 v = *(uint4*)(sm + SMG_C + r * CSTR2 + q * 16);
        *(uint4*)((char*)g_G16 + (size_t)(row0 + r) * 1024 + q * 16) = v;
    }
}

// ---------------- L3: barrier-free HMMA LSTM + mma MLP (h in registers) -------------------
#define SL_B  0
#define SL_W1 (512 * ASTR)                        /* 139264 */
#define SL_TOTAL (SL_W1 + 128 * ASTR)             /* 174080 */
__global__ __launch_bounds__(256, 1) void k_lstm_mma(const int* __restrict__ edges,
                                                     const float* __restrict__ mlp_b1,
                                                     const float* __restrict__ mlp_W2,
                                                     const float* __restrict__ mlp_b2,
                                                     float* __restrict__ scores_out) {
    extern __shared__ char sm[];
    int tid = threadIdx.x, w = tid >> 5, l = tid & 31;

    const uint4* Bg = (const uint4*)g_Bh;
    for (int idx = tid; idx < 512 * 16; idx += 256) {
        int n = idx >> 4, c4 = idx & 15;
        *(uint4*)(sm + SL_B + n * ASTR + c4 * 16) = Bg[(size_t)n * 16 + c4];
    }
    const uint4* Wg = (const uint4*)g_W1h;
    for (int idx = tid; idx < 128 * 16; idx += 256) {
        int n = idx >> 4, c4 = idx & 15;
        *(uint4*)(sm + SL_W1 + n * ASTR + c4 * 16) = Wg[(size_t)n * 16 + c4];
    }
    __syncthreads();

    uint32_t base = s2u(sm);
    int g8 = l & 7, t4 = l & 3, gg = l >> 2;
    // ldmB4 lane address (row/col part); tile adds (g*128 + nt*8)*ASTR + kp*64
    uint32_t bFrag = base + SL_B + (uint32_t)g8 * ASTR
                   + ((l >> 3) & 1) * 16 + ((l >> 4) & 1) * 32;
    uint32_t wFrag = base + SL_W1 + (uint32_t)g8 * ASTR
                   + ((l >> 3) & 1) * 16 + ((l >> 4) & 1) * 32;

    int seqA = blockIdx.x * 128 + w * 16 + gg;
    int seqB = seqA + 8;
    int bA = seqA / Pn, bB = seqB / Pn;

    float cst[64];
#pragma unroll
    for (int q = 0; q < 64; q++) cst[q] = 0.0f;
    uint32_t hf[8][4];
#pragma unroll
    for (int kk = 0; kk < 8; kk++)
#pragma unroll
        for (int q = 0; q < 4; q++) hf[kk][q] = 0u;

    for (int t = 0; t < Tn; t++) {
        int rowGA = (t == 0) ? NPL + bA : (t == 4) ? NPL + Bsz + bA : seqA * Ln + (t - 1);
        int rowGB = (t == 0) ? NPL + bB : (t == 4) ? NPL + Bsz + bB : seqB * Ln + (t - 1);
        int eA = (t < Ln) ? edges[seqA * Ln + t] : 0;
        int eB = (t < Ln) ? edges[seqB * Ln + t] : 0;
        const char* gAr = (const char*)g_G16 + (size_t)rowGA * 1024 + t4 * 16;
        const char* gBr = (const char*)g_G16 + (size_t)rowGB * 1024 + t4 * 16;
        const char* rAr = (const char*)g_relGb16 + (size_t)eA * 1024 + t4 * 16;
        const char* rBr = (const char*)g_relGb16 + (size_t)eB * 1024 + t4 * 16;

        uint32_t hn[8][4];
#pragma unroll
        for (int kt = 0; kt < 8; kt++) {
#pragma unroll
            for (int half = 0; half < 2; half++) {
                int nt = kt * 2 + half;
                uint4 guA = *(const uint4*)(gAr + nt * 64);
                uint4 guB = *(const uint4*)(gBr + nt * 64);
                uint4 ruA = *(const uint4*)(rAr + nt * 64);
                uint4 ruB = *(const uint4*)(rBr + nt * 64);

                float acc[4][4];
#pragma unroll
                for (int g = 0; g < 4; g++)
#pragma unroll
                    for (int q = 0; q < 4; q++) acc[g][q] = 0.0f;
                if (t > 0) {
                    uint32_t tRow = (uint32_t)(nt * 8) * ASTR;
#pragma unroll
                    for (int kp = 0; kp < 4; kp++) {
#pragma unroll
                        for (int g = 0; g < 4; g++) {
                            uint32_t b4[4];
                            ldmB4(b4, bFrag + tRow + (uint32_t)(g * 128) * ASTR + kp * 64);
                            mma16816(acc[g], hf[2 * kp], b4);
                            mma16816(acc[g], hf[2 * kp + 1], b4 + 2);
                        }
                    }
                }
                // gates: guX/ruX = (i0,i1)(f0,f1)(g0,g1)(o0,o1)
                float2 iA = __half22float2(*(const __half2*)&guA.x);
                float2 fA = __half22float2(*(const __half2*)&guA.y);
                float2 gA = __half22float2(*(const __half2*)&guA.z);
                float2 oA = __half22float2(*(const __half2*)&guA.w);
                float2 iB = __half22float2(*(const __half2*)&guB.x);
                float2 fB = __half22float2(*(const __half2*)&guB.y);
                float2 gB = __half22float2(*(const __half2*)&guB.z);
                float2 oB = __half22float2(*(const __half2*)&guB.w);
                float2 riA = __half22float2(*(const __half2*)&ruA.x);
                float2 rfA = __half22float2(*(const __half2*)&ruA.y);
                float2 rgA = __half22float2(*(const __half2*)&ruA.z);
                float2 roA = __half22float2(*(const __half2*)&ruA.w);
                float2 riB = __half22float2(*(const __half2*)&ruB.x);
                float2 rfB = __half22float2(*(const __half2*)&ruB.y);
                float2 rgB = __half22float2(*(const __half2*)&ruB.z);
                float2 roB = __half22float2(*(const __half2*)&ruB.w);

                int ci = nt * 4;
                // row A, j0
                float gi = acc[0][0] + iA.x + riA.x;
                float gf = acc[1][0] + fA.x + rfA.x;
                float gG = acc[2][0] + gA.x + rgA.x;
                float gO = acc[3][0] + oA.x + roA.x;
                cst[ci] = siga(gf) * cst[ci] + siga(gi) * tanha(gG);
                float hA0 = siga(gO) * tanha(cst[ci]);
                // row A, j1
                gi = acc[0][1] + iA.y + riA.y;
                gf = acc[1][1] + fA.y + rfA.y;
                gG = acc[2][1] + gA.y + rgA.y;
                gO = acc[3][1] + oA.y + roA.y;
                cst[ci + 1] = siga(gf) * cst[ci + 1] + siga(gi) * tanha(gG);
                float hA1 = siga(gO) * tanha(cst[ci + 1]);
                // row B, j0
                gi = acc[0][2] + iB.x + riB.x;
                gf = acc[1][2] + fB.x + rfB.x;
                gG = acc[2][2] + gB.x + rgB.x;
                gO = acc[3][2] + oB.x + roB.x;
                cst[ci + 2] = siga(gf) * cst[ci + 2] + siga(gi) * tanha(gG);
                float hB0 = siga(gO) * tanha(cst[ci + 2]);
                // row B, j1
                gi = acc[0][3] + iB.y + riB.y;
                gf = acc[1][3] + fB.y + rfB.y;
                gG = acc[2][3] + gB.y + rgB.y;
                gO = acc[3][3] + oB.y + roB.y;
                cst[ci + 3] = siga(gf) * cst[ci + 3] + siga(gi) * tanha(gG);
                float hB1 = siga(gO) * tanha(cst[ci + 3]);

                __half2 pA = __floats2half2_rn(hA0, hA1);
                __half2 pB = __floats2half2_rn(hB0, hB1);
                hn[kt][half * 2]     = *(uint32_t*)&pA;
                hn[kt][half * 2 + 1] = *(uint32_t*)&pB;
            }
        }
#pragma unroll
        for (int kk = 0; kk < 8; kk++)
#pragma unroll
            for (int q = 0; q < 4; q++) hf[kk][q] = hn[kk][q];
    }

    // ---- MLP via mma on register h-fragments ----
    float sc0 = 0.0f, sc1 = 0.0f;
#pragma unroll
    for (int ntg = 0; ntg < 16; ntg++) {
        float acc[4];
#pragma unroll
        for (int q = 0; q < 4; q++) acc[q] = 0.0f;
        uint32_t tRow = (uint32_t)(ntg * 8) * ASTR;
#pragma unroll
        for (int kp = 0; kp < 4; kp++) {
            uint32_t b4[4];
            ldmB4(b4, wFrag + tRow + kp * 64);
            mma16816(acc, hf[2 * kp], b4);
            mma16816(acc, hf[2 * kp + 1], b4 + 2);
        }
        int j0 = ntg * 8 + t4 * 2;
        float b10 = __ldg(mlp_b1 + j0), b11 = __ldg(mlp_b1 + j0 + 1);
        float w20 = __ldg(mlp_W2 + j0), w21 = __ldg(mlp_W2 + j0 + 1);
        sc0 += fmaxf(acc[0] + b10, 0.0f) * w20 + fmaxf(acc[1] + b11, 0.0f) * w21;
        sc1 += fmaxf(acc[2] + b10, 0.0f) * w20 + fmaxf(acc[3] + b11, 0.0f) * w21;
    }
    sc0 += __shfl_xor_sync(0xffffffffu, sc0, 1);
    sc0 += __shfl_xor_sync(0xffffffffu, sc0, 2);
    sc1 += __shfl_xor_sync(0xffffffffu, sc1, 1);
    sc1 += __shfl_xor_sync(0xffffffffu, sc1, 2);
    if (t4 == 0) {
        float b2 = __ldg(mlp_b2);
        scores_out[seqA] = sc0 + b2;
        scores_out[seqB] = sc1 + b2;
    }
}

// ---------------- L4: logsumexp + BCE ----------------
__global__ void k_final(const float* __restrict__ label, float* __restrict__ out) {
    __shared__ float red[Bsz];
    int b = threadIdx.x;
    const float* sc = out + 1 + Bsz + b * Pn;
    float mx = -1e30f;
#pragma unroll
    for (int p = 0; p < Pn; p++) mx = fmaxf(mx, sc[p] * 0.5f);
    float s = 0.0f;
#pragma unroll
    for (int p = 0; p < Pn; p++) s += expf(sc[p] * 0.5f - mx);
    float lse = mx + logf(s);
    float pr = 1.0f / (1.0f + expf(-lse));
    out[1 + b] = pr;
    float pc = fminf(fmaxf(pr, 1e-7f), 1.0f - 1e-7f);
    float lb = label[b];
    red[b] = -(lb * logf(pc) + (1.0f - lb) * logf(1.0f - pc));
    __syncthreads();
    for (int st = Bsz / 2; st > 0; st >>= 1) {
        if (b < st) red[b] += red[b + st];
        __syncthreads();
    }
    if (b == 0) out[0] = red[0] / (float)Bsz;
}

// ---------------- launch ----------------
extern "C" void kernel_launch(void* const* d_in, const int* in_sizes, int n_in,
                              void* d_out, int out_size) {
    const int*   item1     = (const int*)d_in[0];
    const int*   item2     = (const int*)d_in[1];
    const int*   paths     = (const int*)d_in[2];
    const int*   edges     = (const int*)d_in[3];
    const float* label     = (const float*)d_in[4];
    const float* doc_table = (const float*)d_in[5];
    const float* ent_table = (const float*)d_in[6];
    const float* rel_table = (const float*)d_in[7];
    const float* nc_W1 = (const float*)d_in[8];
    const float* nc_b1 = (const float*)d_in[9];
    const float* nc_W2 = (const float*)d_in[10];
    const float* nc_b2 = (const float*)d_in[11];
    const float* ec_W  = (const float*)d_in[12];
    const float* ec_b  = (const float*)d_in[13];
    const float* rc_W  = (const float*)d_in[14];
    const float* rc_b  = (const float*)d_in[15];
    const float* W_ih  = (const float*)d_in[16];
    const float* W_hh  = (const float*)d_in[17];
    const float* b_ih  = (const float*)d_in[18];
    const float* b_hh  = (const float*)d_in[19];
    const float* mlp_W1 = (const float*)d_in[20];
    const float* mlp_b1 = (const float*)d_in[21];
    const float* mlp_W2 = (const float*)d_in[22];
    const float* mlp_b2 = (const float*)d_in[23];
    float* out = (float*)d_out;

    cudaFuncSetAttribute(k_compress_rel, cudaFuncAttributeMaxDynamicSharedMemorySize, SMC_TOTAL);
    cudaFuncSetAttribute(k_gemm_mma, cudaFuncAttributeMaxDynamicSharedMemorySize, SMG_TOTAL);
    cudaFuncSetAttribute(k_lstm_mma, cudaFuncAttributeMaxDynamicSharedMemorySize, SL_TOTAL);

    k_news_transpose<<<768, 128>>>(item1, item2, doc_table, nc_W1, nc_b1, nc_W2, nc_b2,
                                   W_ih, W_hh, ec_W, mlp_W1);
    k_compress_rel<<<NPL / 128 + NREL, 512, SMC_TOTAL>>>(paths, ent_table, ec_b,
                                                         rel_table, rc_W, rc_b, b_ih, b_hh);
    k_gemm_mma<<<MTOT / 128, 512, SMG_TOTAL>>>();
    k_lstm_mma<<<Nseq / 128, 256, SL_TOTAL>>>(edges, mlp_b1, mlp_W2, mlp_b2, out + 1 + Bsz);
    k_final<<<1, Bsz>>>(label, out);
}